// round 1
// baseline (speedup 1.0000x reference)
#include <cuda_runtime.h>
#include <cuda_bf16.h>
#include <cstdint>

#define N_ROWS 4096
#define DIM    1024
#define VOCAB  50257
#define LR     64
#define NCAND  2048
#define CH     32
#define NCHUNK 128
#define NBINS  4096
#define LSCALE 20.0f
#define AUXW   0.2f
#define TN     128

// ---------------- persistent device scratch (static, no allocation) -------------
__device__ __nv_bfloat16 g_W[(size_t)VOCAB * DIM];   // raw embedding, bf16 (103MB)
__device__ float g_winv[VOCAB];                      // 1/||W_row||_full
__device__ float g_wlinv[VOCAB];                     // 1/||W_row[:64]||
__device__ __nv_bfloat16 g_H[(size_t)N_ROWS * DIM];  // normalized hidden, bf16
__device__ float g_hinv[N_ROWS];
__device__ float g_hmean[NCHUNK * LR];
__device__ float g_scan[(size_t)NCHUNK * VOCAB];     // 25.7MB
__device__ int   g_hist[NCHUNK * NBINS];
__device__ int   g_thr[NCHUNK];
__device__ int   g_above[NCHUNK];
__device__ int   g_cntA[NCHUNK];
__device__ int   g_cntB[NCHUNK];
__device__ int   g_cand[NCHUNK * NCAND];
__device__ float g_posf[N_ROWS];
__device__ float g_posl[N_ROWS];
__device__ float g_sumf[N_ROWS];
__device__ float g_suml[N_ROWS];

// ---------------- helpers -------------------------------------------------------
__device__ __forceinline__ unsigned long long ffma2(unsigned long long a,
                                                    unsigned long long b,
                                                    unsigned long long c) {
    unsigned long long d;
    asm("fma.rn.f32x2 %0, %1, %2, %3;" : "=l"(d) : "l"(a), "l"(b), "l"(c));
    return d;
}
__device__ __forceinline__ unsigned long long pack2(float2 f) {
    unsigned long long r;
    asm("mov.b64 %0, {%1,%2};" : "=l"(r) : "f"(f.x), "f"(f.y));
    return r;
}
__device__ __forceinline__ float2 unpack2(unsigned long long u) {
    float2 f;
    asm("mov.b64 {%0,%1}, %2;" : "=f"(f.x), "=f"(f.y) : "l"(u));
    return f;
}
__device__ __forceinline__ float2 bf2f2(unsigned int u) {
    __nv_bfloat162 h = *reinterpret_cast<__nv_bfloat162*>(&u);
    return __bfloat1622float2(h);
}
__device__ __forceinline__ unsigned int f2bf2u(float a, float b) {
    __nv_bfloat162 h = __floats2bfloat162_rn(a, b);
    return *reinterpret_cast<unsigned int*>(&h);
}
__device__ __forceinline__ int binof(float v) {
    int b = (int)floorf((v + 0.25f) * 8192.0f);
    return b < 0 ? 0 : (b > NBINS - 1 ? NBINS - 1 : b);
}
// block-wide sum, broadcast to all threads. sbuf must hold 33 floats.
__device__ __forceinline__ float block_sum_bcast(float v, float* sbuf) {
    int lane = threadIdx.x & 31, wid = threadIdx.x >> 5;
#pragma unroll
    for (int o = 16; o; o >>= 1) v += __shfl_down_sync(0xffffffffu, v, o);
    if (lane == 0) sbuf[wid] = v;
    __syncthreads();
    if (threadIdx.x == 0) {
        float r = sbuf[0];
        int nw = (int)(blockDim.x >> 5);
        for (int i = 1; i < nw; ++i) r += sbuf[i];
        sbuf[32] = r;
    }
    __syncthreads();
    return sbuf[32];
}

// ---------------- kernels -------------------------------------------------------
__global__ void k_zero() {
    int i = blockIdx.x * blockDim.x + threadIdx.x;
    if (i < NCHUNK * NBINS) g_hist[i] = 0;
    if (i < NCHUNK * LR) g_hmean[i] = 0.f;
    if (i < NCHUNK) { g_cntA[i] = 0; g_cntB[i] = 0; }
    if (i < N_ROWS) { g_sumf[i] = 0.f; g_suml[i] = 0.f; }
}

__global__ void __launch_bounds__(256) k_prep_w(const float* __restrict__ W) {
    __shared__ float sbuf[33];
    int v = blockIdx.x;
    int t = threadIdx.x;
    const float4 x = reinterpret_cast<const float4*>(W + (size_t)v * DIM)[t];
    float ss = x.x * x.x + x.y * x.y + x.z * x.z + x.w * x.w;
    float ssl = (t < 16) ? ss : 0.f;
    float tot = block_sum_bcast(ss, sbuf);
    float totl = block_sum_bcast(ssl, sbuf);
    if (t == 0) {
        g_winv[v] = rsqrtf(fmaxf(tot, 1e-24f));
        g_wlinv[v] = rsqrtf(fmaxf(totl, 1e-24f));
    }
    uint2 u;
    u.x = f2bf2u(x.x, x.y);
    u.y = f2bf2u(x.z, x.w);
    *reinterpret_cast<uint2*>(&g_W[(size_t)v * DIM + 4 * t]) = u;
}

__global__ void __launch_bounds__(256) k_prep_h(const float* __restrict__ H) {
    __shared__ float sbuf[33];
    int r = blockIdx.x;
    int t = threadIdx.x;
    const float4 x = reinterpret_cast<const float4*>(H + (size_t)r * DIM)[t];
    float ss = x.x * x.x + x.y * x.y + x.z * x.z + x.w * x.w;
    float tot = block_sum_bcast(ss, sbuf);
    float inv = 1.f / fmaxf(sqrtf(tot), 1e-6f);
    uint2 u;
    u.x = f2bf2u(x.x * inv, x.y * inv);
    u.y = f2bf2u(x.z * inv, x.w * inv);
    *reinterpret_cast<uint2*>(&g_H[(size_t)r * DIM + 4 * t]) = u;
    if (t == 0) g_hinv[r] = inv;
    if (t < 16) {
        int c = r >> 5;
        const float w = inv * (1.f / 32.f);
        atomicAdd(&g_hmean[c * LR + 4 * t + 0], x.x * w);
        atomicAdd(&g_hmean[c * LR + 4 * t + 1], x.y * w);
        atomicAdd(&g_hmean[c * LR + 4 * t + 2], x.z * w);
        atomicAdd(&g_hmean[c * LR + 4 * t + 3], x.w * w);
    }
}

__global__ void __launch_bounds__(256) k_pos(const float* __restrict__ H,
                                             const float* __restrict__ W,
                                             const int* __restrict__ tg) {
    __shared__ float sbuf[33];
    int r = blockIdx.x;
    int t = threadIdx.x;
    int tgt = tg[r];
    const float4 hx = reinterpret_cast<const float4*>(H + (size_t)r * DIM)[t];
    const float4 wx = reinterpret_cast<const float4*>(W + (size_t)tgt * DIM)[t];
    float d = hx.x * wx.x + hx.y * wx.y + hx.z * wx.z + hx.w * wx.w;
    float dl = (t < 16) ? d : 0.f;
    float td = block_sum_bcast(d, sbuf);
    float tdl = block_sum_bcast(dl, sbuf);
    if (t == 0) {
        float hi = g_hinv[r];
        g_posf[r] = td * hi * g_winv[tgt];
        g_posl[r] = tdl * hi * g_wlinv[tgt];
    }
}

// scan logits for all chunks + histogram (f32x2 packed)
__global__ void __launch_bounds__(256) k_scan() {
    __shared__ unsigned long long s_hm2[NCHUNK * 32];  // 32KB: (c, kpair) -> float2
    int tid = threadIdx.x;
    for (int i = tid; i < NCHUNK * 32; i += 256)
        s_hm2[i] = pack2(make_float2(g_hmean[2 * i], g_hmean[2 * i + 1]));
    __syncthreads();
    int v = blockIdx.x * 256 + tid;
    if (v >= VOCAB) return;
    unsigned long long wv2[32];
    const unsigned int* wr = reinterpret_cast<const unsigned int*>(g_W + (size_t)v * DIM);
#pragma unroll
    for (int kp = 0; kp < 32; ++kp) wv2[kp] = pack2(bf2f2(wr[kp]));
    float wli = g_wlinv[v];
    for (int c = 0; c < NCHUNK; ++c) {
        unsigned long long acc = 0ull;
#pragma unroll
        for (int kp = 0; kp < 32; ++kp) acc = ffma2(wv2[kp], s_hm2[c * 32 + kp], acc);
        float2 f = unpack2(acc);
        float val = (f.x + f.y) * wli;
        g_scan[(size_t)c * VOCAB + v] = val;
        atomicAdd(&g_hist[c * NBINS + binof(val)], 1);
    }
}

__global__ void __launch_bounds__(256) k_thresh() {
    __shared__ int part[256];
    int c = blockIdx.x;
    int t = threadIdx.x;
    int s = 0;
    for (int b = t * 16; b < t * 16 + 16; ++b) s += g_hist[c * NBINS + b];
    part[t] = s;
    __syncthreads();
    if (t == 0) {
        int cum = 0, T = 0, above = 0;
        for (int p = 255; p >= 0; --p) {
            if (cum + part[p] >= NCAND) {
                int c2 = cum;
                for (int b = p * 16 + 15; b >= p * 16; --b) {
                    int h = g_hist[c * NBINS + b];
                    if (c2 + h >= NCAND) { T = b; above = c2; break; }
                    c2 += h;
                }
                break;
            }
            cum += part[p];
        }
        g_thr[c] = T;
        g_above[c] = above;
    }
}

__global__ void __launch_bounds__(256) k_collect() {
    int v = blockIdx.x * 256 + threadIdx.x;
    int c = blockIdx.y;
    if (v >= VOCAB) return;
    float val = g_scan[(size_t)c * VOCAB + v];
    int b = binof(val);
    int T = g_thr[c];
    if (b > T) {
        int p = atomicAdd(&g_cntA[c], 1);
        if (p < NCAND) g_cand[c * NCAND + p] = v;
    } else if (b == T) {
        int above = g_above[c];
        int need = NCAND - above;
        int j = atomicAdd(&g_cntB[c], 1);
        if (j < need) g_cand[c * NCAND + above + j] = v;
    }
}

// main fused GEMM (full K=1024 + low K=64 prefix) + masked exp-sum
__global__ void __launch_bounds__(256) k_main(const int* __restrict__ tg) {
    __shared__ unsigned long long sA[32][33];       // [kpair][row]
    __shared__ unsigned long long sB[32][TN + 1];   // [kpair][cand]
    __shared__ int sc[TN];
    __shared__ float swf[TN], swl[TN];
    __shared__ int stgt[CH];
    __shared__ float sredF[CH], sredL[CH];

    int tid = threadIdx.x;
    int chunk = blockIdx.y;
    int nb = blockIdx.x;

    if (tid < TN) {
        int cid = g_cand[chunk * NCAND + nb * TN + tid];
        sc[tid] = cid;
        swf[tid] = g_winv[cid];
        swl[tid] = g_wlinv[cid];
    } else if (tid < TN + CH) {
        int r = tid - TN;
        stgt[r] = tg[chunk * CH + r];
        sredF[r] = 0.f;
        sredL[r] = 0.f;
    }

    unsigned long long accF[16], accL[16];
#pragma unroll
    for (int i = 0; i < 16; ++i) { accF[i] = 0ull; accL[i] = 0ull; }

    int r0 = (tid & 7) * 4;
    int c0 = (tid >> 3) * 4;
    const size_t hbase = (size_t)(chunk * CH) * DIM;

    for (int s = 0; s < 16; ++s) {
        int k0 = s * 64;
        __syncthreads();
        for (int i = tid; i < 32 * 32; i += 256) {
            int row = i >> 5, kp = i & 31;
            unsigned int u = *reinterpret_cast<const unsigned int*>(
                &g_H[hbase + (size_t)row * DIM + k0 + 2 * kp]);
            sA[kp][row] = pack2(bf2f2(u));
        }
        for (int i = tid; i < TN * 32; i += 256) {
            int j = i >> 5, kp = i & 31;
            unsigned int u = *reinterpret_cast<const unsigned int*>(
                &g_W[(size_t)sc[j] * DIM + k0 + 2 * kp]);
            sB[kp][j] = pack2(bf2f2(u));
        }
        __syncthreads();
#pragma unroll
        for (int kp = 0; kp < 32; ++kp) {
            unsigned long long a0 = sA[kp][r0], a1 = sA[kp][r0 + 1];
            unsigned long long a2 = sA[kp][r0 + 2], a3 = sA[kp][r0 + 3];
            unsigned long long b0 = sB[kp][c0], b1 = sB[kp][c0 + 1];
            unsigned long long b2 = sB[kp][c0 + 2], b3 = sB[kp][c0 + 3];
            accF[0] = ffma2(a0, b0, accF[0]);
            accF[1] = ffma2(a0, b1, accF[1]);
            accF[2] = ffma2(a0, b2, accF[2]);
            accF[3] = ffma2(a0, b3, accF[3]);
            accF[4] = ffma2(a1, b0, accF[4]);
            accF[5] = ffma2(a1, b1, accF[5]);
            accF[6] = ffma2(a1, b2, accF[6]);
            accF[7] = ffma2(a1, b3, accF[7]);
            accF[8] = ffma2(a2, b0, accF[8]);
            accF[9] = ffma2(a2, b1, accF[9]);
            accF[10] = ffma2(a2, b2, accF[10]);
            accF[11] = ffma2(a2, b3, accF[11]);
            accF[12] = ffma2(a3, b0, accF[12]);
            accF[13] = ffma2(a3, b1, accF[13]);
            accF[14] = ffma2(a3, b2, accF[14]);
            accF[15] = ffma2(a3, b3, accF[15]);
        }
        if (s == 0) {
#pragma unroll
            for (int i = 0; i < 16; ++i) accL[i] = accF[i];
        }
    }

    float rsF[4] = {0.f, 0.f, 0.f, 0.f};
    float rsL[4] = {0.f, 0.f, 0.f, 0.f};
#pragma unroll
    for (int i = 0; i < 4; ++i) {
        int t = stgt[r0 + i];
#pragma unroll
        for (int j = 0; j < 4; ++j) {
            int cj = sc[c0 + j];
            float2 f = unpack2(accF[i * 4 + j]);
            float2 g = unpack2(accL[i * 4 + j]);
            float simf = (f.x + f.y) * swf[c0 + j];
            float siml = (g.x + g.y) * swl[c0 + j];
            if (cj != t) {
                rsF[i] += __expf(LSCALE * simf);
                rsL[i] += __expf(LSCALE * siml);
            }
        }
    }
#pragma unroll
    for (int i = 0; i < 4; ++i) {
        atomicAdd(&sredF[r0 + i], rsF[i]);
        atomicAdd(&sredL[r0 + i], rsL[i]);
    }
    __syncthreads();
    if (tid < CH) {
        atomicAdd(&g_sumf[chunk * CH + tid], sredF[tid]);
        atomicAdd(&g_suml[chunk * CH + tid], sredL[tid]);
    }
}

__global__ void __launch_bounds__(256) k_final(float* __restrict__ out) {
    __shared__ float sbuf[33];
    float acc = 0.f;
    for (int i = threadIdx.x; i < N_ROWS; i += 256) {
        float pf = g_posf[i], pl = g_posl[i];
        float lf = logf(__expf(LSCALE * pf) + g_sumf[i]) - LSCALE * pf;
        float ll = logf(__expf(LSCALE * pl) + g_suml[i]) - LSCALE * pl;
        acc += lf + AUXW * ll;
    }
    float tot = block_sum_bcast(acc, sbuf);
    if (threadIdx.x == 0) out[0] = tot * (1.0f / (float)N_ROWS);
}

// ---------------- launch --------------------------------------------------------
extern "C" void kernel_launch(void* const* d_in, const int* in_sizes, int n_in,
                              void* d_out, int out_size) {
    const float* h = (const float*)d_in[0];
    const float* w = (const float*)d_in[1];
    const int* tg = (const int*)d_in[2];
    float* out = (float*)d_out;
    (void)in_sizes; (void)n_in; (void)out_size;

    k_zero<<<(NCHUNK * NBINS + 255) / 256, 256>>>();
    k_prep_w<<<VOCAB, 256>>>(w);
    k_prep_h<<<N_ROWS, 256>>>(h);
    k_pos<<<N_ROWS, 256>>>(h, w, tg);
    k_scan<<<(VOCAB + 255) / 256, 256>>>();
    k_thresh<<<NCHUNK, 256>>>();
    k_collect<<<dim3((VOCAB + 255) / 256, NCHUNK), 256>>>();
    k_main<<<dim3(NCAND / TN, NCHUNK), 256>>>(tg);
    k_final<<<1, 256>>>(out);
}

// round 6
// speedup vs baseline: 3.6190x; 3.6190x over previous
#include <cuda_runtime.h>
#include <cuda_bf16.h>
#include <cstdint>

#define N_ROWS 4096
#define DIM    1024
#define VOCAB  50257
#define LR     64
#define NCAND  2048
#define CH     32
#define NCHUNK 128
#define NBINS  4096
#define LSCALE 20.0f
#define AUXW   0.2f
#define TM     128   // candidates per block (MMA M)
#define KSTEP  64    // K elements per smem stage (128 bytes bf16)
#define NSTAGE (DIM / KSTEP)

// ---------------- persistent device scratch (static, no allocation) -------------
__device__ __nv_bfloat16 g_W[(size_t)VOCAB * DIM];   // raw embedding, bf16 (103MB)
__device__ float g_winv[VOCAB];                      // 1/||W_row||_full
__device__ float g_wlinv[VOCAB];                     // 1/||W_row[:64]||
__device__ __nv_bfloat16 g_H[(size_t)N_ROWS * DIM];  // normalized hidden, bf16
__device__ float g_hinv[N_ROWS];
__device__ float g_hmean[NCHUNK * LR];
__device__ float g_scan[(size_t)NCHUNK * VOCAB];     // 25.7MB
__device__ int   g_hist[NCHUNK * NBINS];
__device__ int   g_thr[NCHUNK];
__device__ int   g_above[NCHUNK];
__device__ int   g_cntA[NCHUNK];
__device__ int   g_cntB[NCHUNK];
__device__ int   g_cand[NCHUNK * NCAND];
__device__ float g_posf[N_ROWS];
__device__ float g_posl[N_ROWS];
__device__ float g_sumf[N_ROWS];
__device__ float g_suml[N_ROWS];

// ---------------- helpers -------------------------------------------------------
__device__ __forceinline__ unsigned long long ffma2(unsigned long long a,
                                                    unsigned long long b,
                                                    unsigned long long c) {
    unsigned long long d;
    asm("fma.rn.f32x2 %0, %1, %2, %3;" : "=l"(d) : "l"(a), "l"(b), "l"(c));
    return d;
}
__device__ __forceinline__ unsigned long long pack2(float2 f) {
    unsigned long long r;
    asm("mov.b64 %0, {%1,%2};" : "=l"(r) : "f"(f.x), "f"(f.y));
    return r;
}
__device__ __forceinline__ float2 unpack2(unsigned long long u) {
    float2 f;
    asm("mov.b64 {%0,%1}, %2;" : "=f"(f.x), "=f"(f.y) : "l"(u));
    return f;
}
__device__ __forceinline__ float2 bf2f2(unsigned int u) {
    __nv_bfloat162 h = *reinterpret_cast<__nv_bfloat162*>(&u);
    return __bfloat1622float2(h);
}
__device__ __forceinline__ unsigned int f2bf2u(float a, float b) {
    __nv_bfloat162 h = __floats2bfloat162_rn(a, b);
    return *reinterpret_cast<unsigned int*>(&h);
}
__device__ __forceinline__ int binof(float v) {
    int b = (int)floorf((v + 0.25f) * 8192.0f);
    return b < 0 ? 0 : (b > NBINS - 1 ? NBINS - 1 : b);
}
__device__ __forceinline__ float block_sum_bcast(float v, float* sbuf) {
    int lane = threadIdx.x & 31, wid = threadIdx.x >> 5;
#pragma unroll
    for (int o = 16; o; o >>= 1) v += __shfl_down_sync(0xffffffffu, v, o);
    if (lane == 0) sbuf[wid] = v;
    __syncthreads();
    if (threadIdx.x == 0) {
        float r = sbuf[0];
        int nw = (int)(blockDim.x >> 5);
        for (int i = 1; i < nw; ++i) r += sbuf[i];
        sbuf[32] = r;
    }
    __syncthreads();
    return sbuf[32];
}
__device__ __forceinline__ uint32_t smem_u32(const void* p) {
    uint32_t a;
    asm("{ .reg .u64 t; cvta.to.shared.u64 t, %1; cvt.u32.u64 %0, t; }"
        : "=r"(a) : "l"(p));
    return a;
}
__device__ __forceinline__ uint32_t sw128(uint32_t off) {
    return off ^ ((off >> 3) & 0x70);
}
__device__ __forceinline__ void ldmat4(uint32_t& r0, uint32_t& r1, uint32_t& r2,
                                       uint32_t& r3, uint32_t addr) {
    asm volatile("ldmatrix.sync.aligned.m8n8.x4.shared.b16 {%0,%1,%2,%3}, [%4];"
                 : "=r"(r0), "=r"(r1), "=r"(r2), "=r"(r3) : "r"(addr));
}
__device__ __forceinline__ void mma16816(float* c, const uint32_t* a,
                                         const uint32_t* b) {
    asm volatile(
        "mma.sync.aligned.m16n8k16.row.col.f32.bf16.bf16.f32 "
        "{%0,%1,%2,%3}, {%4,%5,%6,%7}, {%8,%9}, {%0,%1,%2,%3};"
        : "+f"(c[0]), "+f"(c[1]), "+f"(c[2]), "+f"(c[3])
        : "r"(a[0]), "r"(a[1]), "r"(a[2]), "r"(a[3]), "r"(b[0]), "r"(b[1]));
}

// ---------------- kernels -------------------------------------------------------
__global__ void k_zero() {
    int i = blockIdx.x * blockDim.x + threadIdx.x;
    if (i < NCHUNK * NBINS) g_hist[i] = 0;
    if (i < NCHUNK * LR) g_hmean[i] = 0.f;
    if (i < NCHUNK) { g_cntA[i] = 0; g_cntB[i] = 0; }
    if (i < N_ROWS) { g_sumf[i] = 0.f; g_suml[i] = 0.f; }
}

__global__ void __launch_bounds__(256) k_prep_w(const float* __restrict__ W) {
    __shared__ float sbuf[33];
    int v = blockIdx.x;
    int t = threadIdx.x;
    const float4 x = reinterpret_cast<const float4*>(W + (size_t)v * DIM)[t];
    float ss = x.x * x.x + x.y * x.y + x.z * x.z + x.w * x.w;
    float ssl = (t < 16) ? ss : 0.f;
    float tot = block_sum_bcast(ss, sbuf);
    float totl = block_sum_bcast(ssl, sbuf);
    if (t == 0) {
        g_winv[v] = rsqrtf(fmaxf(tot, 1e-24f));
        g_wlinv[v] = rsqrtf(fmaxf(totl, 1e-24f));
    }
    uint2 u;
    u.x = f2bf2u(x.x, x.y);
    u.y = f2bf2u(x.z, x.w);
    *reinterpret_cast<uint2*>(&g_W[(size_t)v * DIM + 4 * t]) = u;
}

__global__ void __launch_bounds__(256) k_prep_h(const float* __restrict__ H) {
    __shared__ float sbuf[33];
    int r = blockIdx.x;
    int t = threadIdx.x;
    const float4 x = reinterpret_cast<const float4*>(H + (size_t)r * DIM)[t];
    float ss = x.x * x.x + x.y * x.y + x.z * x.z + x.w * x.w;
    float tot = block_sum_bcast(ss, sbuf);
    float inv = 1.f / fmaxf(sqrtf(tot), 1e-6f);
    uint2 u;
    u.x = f2bf2u(x.x * inv, x.y * inv);
    u.y = f2bf2u(x.z * inv, x.w * inv);
    *reinterpret_cast<uint2*>(&g_H[(size_t)r * DIM + 4 * t]) = u;
    if (t == 0) g_hinv[r] = inv;
    if (t < 16) {
        int c = r >> 5;
        const float w = inv * (1.f / 32.f);
        atomicAdd(&g_hmean[c * LR + 4 * t + 0], x.x * w);
        atomicAdd(&g_hmean[c * LR + 4 * t + 1], x.y * w);
        atomicAdd(&g_hmean[c * LR + 4 * t + 2], x.z * w);
        atomicAdd(&g_hmean[c * LR + 4 * t + 3], x.w * w);
    }
}

__global__ void __launch_bounds__(256) k_pos(const float* __restrict__ H,
                                             const float* __restrict__ W,
                                             const int* __restrict__ tg) {
    __shared__ float sbuf[33];
    int r = blockIdx.x;
    int t = threadIdx.x;
    int tgt = tg[r];
    const float4 hx = reinterpret_cast<const float4*>(H + (size_t)r * DIM)[t];
    const float4 wx = reinterpret_cast<const float4*>(W + (size_t)tgt * DIM)[t];
    float d = hx.x * wx.x + hx.y * wx.y + hx.z * wx.z + hx.w * wx.w;
    float dl = (t < 16) ? d : 0.f;
    float td = block_sum_bcast(d, sbuf);
    float tdl = block_sum_bcast(dl, sbuf);
    if (t == 0) {
        float hi = g_hinv[r];
        g_posf[r] = td * hi * g_winv[tgt];
        g_posl[r] = tdl * hi * g_wlinv[tgt];
    }
}

// scan logits + histogram; grid.y splits the chunk loop for occupancy
__global__ void __launch_bounds__(256) k_scan() {
    __shared__ unsigned long long s_hm2[NCHUNK * 32];
    int tid = threadIdx.x;
    for (int i = tid; i < NCHUNK * 32; i += 256)
        s_hm2[i] = pack2(make_float2(g_hmean[2 * i], g_hmean[2 * i + 1]));
    __syncthreads();
    int v = blockIdx.x * 256 + tid;
    if (v >= VOCAB) return;
    unsigned long long wv2[32];
    const unsigned int* wr = reinterpret_cast<const unsigned int*>(g_W + (size_t)v * DIM);
#pragma unroll
    for (int kp = 0; kp < 32; ++kp) wv2[kp] = pack2(bf2f2(wr[kp]));
    float wli = g_wlinv[v];
    int c0 = blockIdx.y * (NCHUNK / 4);
    for (int c = c0; c < c0 + NCHUNK / 4; ++c) {
        unsigned long long acc = 0ull;
#pragma unroll
        for (int kp = 0; kp < 32; ++kp) acc = ffma2(wv2[kp], s_hm2[c * 32 + kp], acc);
        float2 f = unpack2(acc);
        float val = (f.x + f.y) * wli;
        g_scan[(size_t)c * VOCAB + v] = val;
        atomicAdd(&g_hist[c * NBINS + binof(val)], 1);
    }
}

__global__ void __launch_bounds__(256) k_thresh() {
    __shared__ int part[256];
    int c = blockIdx.x;
    int t = threadIdx.x;
    int s = 0;
    for (int b = t * 16; b < t * 16 + 16; ++b) s += g_hist[c * NBINS + b];
    part[t] = s;
    __syncthreads();
    if (t == 0) {
        int cum = 0, T = 0, above = 0;
        for (int p = 255; p >= 0; --p) {
            if (cum + part[p] >= NCAND) {
                int c2 = cum;
                for (int b = p * 16 + 15; b >= p * 16; --b) {
                    int h = g_hist[c * NBINS + b];
                    if (c2 + h >= NCAND) { T = b; above = c2; break; }
                    c2 += h;
                }
                break;
            }
            cum += part[p];
        }
        g_thr[c] = T;
        g_above[c] = above;
    }
}

__global__ void __launch_bounds__(256) k_collect() {
    int v = blockIdx.x * 256 + threadIdx.x;
    int c = blockIdx.y;
    if (v >= VOCAB) return;
    float val = g_scan[(size_t)c * VOCAB + v];
    int b = binof(val);
    int T = g_thr[c];
    if (b > T) {
        int p = atomicAdd(&g_cntA[c], 1);
        if (p < NCAND) g_cand[c * NCAND + p] = v;
    } else if (b == T) {
        int above = g_above[c];
        int need = NCAND - above;
        int j = atomicAdd(&g_cntB[c], 1);
        if (j < need) g_cand[c * NCAND + above + j] = v;
    }
}

// -------- main GEMM: mma.sync bf16, M=128 cand x N=32 rows x K=1024 -------------
// Warp w computes candidate rows [16w,16w+16) x all 32 hidden rows.
// Dual accumulators: accF (full K) and accL (K<64 prefix, stage 0 only).
__global__ void __launch_bounds__(256) k_main(const int* __restrict__ tg) {
    __shared__ __align__(1024) __nv_bfloat16 shA[2][TM * KSTEP];  // 2 x 16KB
    __shared__ __align__(1024) __nv_bfloat16 shB[2][CH * KSTEP];  // 2 x 4KB
    __shared__ int sc[TM];
    __shared__ float swf[TM], swl[TM];
    __shared__ int stgt[CH];
    __shared__ float sredF[CH], sredL[CH];

    const int tid = threadIdx.x;
    const int chunk = blockIdx.y;
    const int nb = blockIdx.x;
    const int w = tid >> 5, lane = tid & 31;

    if (tid < TM) {
        int cid = g_cand[chunk * NCAND + nb * TM + tid];
        sc[tid] = cid;
        swf[tid] = g_winv[cid];
        swl[tid] = g_wlinv[cid];
    } else if (tid < TM + CH) {
        int r = tid - TM;
        stgt[r] = tg[chunk * CH + r];
        sredF[r] = 0.f;
        sredL[r] = 0.f;
    }
    __syncthreads();

    const size_t hbase = (size_t)(chunk * CH) * DIM;
    uint4 pa[4];
    uint4 pb;

    auto PF = [&](int s) {
        int k0 = s * KSTEP;
#pragma unroll
        for (int r = 0; r < 4; ++r) {
            int i = tid + 256 * r;
            int row = i >> 3, seg = i & 7;
            pa[r] = *reinterpret_cast<const uint4*>(
                g_W + (size_t)sc[row] * DIM + k0 + seg * 8);
        }
        {
            int row = tid >> 3, seg = tid & 7;
            pb = *reinterpret_cast<const uint4*>(
                g_H + hbase + (size_t)row * DIM + k0 + seg * 8);
        }
    };
    auto ST = [&](int s) {
        char* A = (char*)shA[s & 1];
        char* B = (char*)shB[s & 1];
#pragma unroll
        for (int r = 0; r < 4; ++r) {
            int i = tid + 256 * r;
            int row = i >> 3, seg = i & 7;
            *reinterpret_cast<uint4*>(A + sw128((uint32_t)(row * 128 + seg * 16))) = pa[r];
        }
        {
            int row = tid >> 3, seg = tid & 7;
            *reinterpret_cast<uint4*>(B + sw128((uint32_t)(row * 128 + seg * 16))) = pb;
        }
    };

    float accF[4][4] = {};
    float accL[4][4] = {};

    auto CMP = [&](int s) {
        uint32_t baseA = smem_u32(shA[s & 1]);
        uint32_t baseB = smem_u32(shB[s & 1]);
#pragma unroll
        for (int kk = 0; kk < 4; ++kk) {
            uint32_t a[4];
            {
                int row = 16 * w + (lane & 15);
                int byteo = kk * 32 + ((lane & 16) ? 16 : 0);
                ldmat4(a[0], a[1], a[2], a[3],
                       baseA + sw128((uint32_t)(row * 128 + byteo)));
            }
            uint32_t b[8];
#pragma unroll
            for (int p = 0; p < 2; ++p) {
                int row = p * 16 + (lane & 7) + ((lane & 16) ? 8 : 0);
                int byteo = kk * 32 + ((lane & 8) ? 16 : 0);
                ldmat4(b[p * 4 + 0], b[p * 4 + 1], b[p * 4 + 2], b[p * 4 + 3],
                       baseB + sw128((uint32_t)(row * 128 + byteo)));
            }
#pragma unroll
            for (int t4 = 0; t4 < 4; ++t4) mma16816(accF[t4], a, &b[t4 * 2]);
            if (s == 0) {
#pragma unroll
                for (int t4 = 0; t4 < 4; ++t4) mma16816(accL[t4], a, &b[t4 * 2]);
            }
        }
    };

    PF(0);
    ST(0);
    __syncthreads();
    for (int s = 0; s < NSTAGE; ++s) {
        if (s < NSTAGE - 1) PF(s + 1);
        CMP(s);
        __syncthreads();
        if (s < NSTAGE - 1) {
            ST(s + 1);
            __syncthreads();
        }
    }

    // epilogue: mask -> exp -> reduce over M (xor-shuffle) -> smem atomics
    {
        int m0 = 16 * w + (lane >> 2), m1 = m0 + 8;
        int c0id = sc[m0], c1id = sc[m1];
        float if0 = swf[m0], if1 = swf[m1];
        float il0 = swl[m0], il1 = swl[m1];
#pragma unroll
        for (int t4 = 0; t4 < 4; ++t4) {
            int n0 = t4 * 8 + 2 * (lane & 3);
            int t0 = stgt[n0], t1 = stgt[n0 + 1];
            float v0 = ((c0id == t0) ? 0.f : __expf(LSCALE * accF[t4][0] * if0)) +
                       ((c1id == t0) ? 0.f : __expf(LSCALE * accF[t4][2] * if1));
            float v1 = ((c0id == t1) ? 0.f : __expf(LSCALE * accF[t4][1] * if0)) +
                       ((c1id == t1) ? 0.f : __expf(LSCALE * accF[t4][3] * if1));
            float l0 = ((c0id == t0) ? 0.f : __expf(LSCALE * accL[t4][0] * il0)) +
                       ((c1id == t0) ? 0.f : __expf(LSCALE * accL[t4][2] * il1));
            float l1 = ((c0id == t1) ? 0.f : __expf(LSCALE * accL[t4][1] * il0)) +
                       ((c1id == t1) ? 0.f : __expf(LSCALE * accL[t4][3] * il1));
#pragma unroll
            for (int o = 4; o < 32; o <<= 1) {
                v0 += __shfl_xor_sync(0xffffffffu, v0, o);
                v1 += __shfl_xor_sync(0xffffffffu, v1, o);
                l0 += __shfl_xor_sync(0xffffffffu, l0, o);
                l1 += __shfl_xor_sync(0xffffffffu, l1, o);
            }
            if (lane < 4) {
                atomicAdd(&sredF[n0], v0);
                atomicAdd(&sredF[n0 + 1], v1);
                atomicAdd(&sredL[n0], l0);
                atomicAdd(&sredL[n0 + 1], l1);
            }
        }
    }
    __syncthreads();
    if (tid < CH) {
        atomicAdd(&g_sumf[chunk * CH + tid], sredF[tid]);
        atomicAdd(&g_suml[chunk * CH + tid], sredL[tid]);
    }
}

__global__ void __launch_bounds__(256) k_final(float* __restrict__ out) {
    __shared__ float sbuf[33];
    float acc = 0.f;
    for (int i = threadIdx.x; i < N_ROWS; i += 256) {
        float pf = g_posf[i], pl = g_posl[i];
        float lf = logf(__expf(LSCALE * pf) + g_sumf[i]) - LSCALE * pf;
        float ll = logf(__expf(LSCALE * pl) + g_suml[i]) - LSCALE * pl;
        acc += lf + AUXW * ll;
    }
    float tot = block_sum_bcast(acc, sbuf);
    if (threadIdx.x == 0) out[0] = tot * (1.0f / (float)N_ROWS);
}

// ---------------- launch --------------------------------------------------------
extern "C" void kernel_launch(void* const* d_in, const int* in_sizes, int n_in,
                              void* d_out, int out_size) {
    const float* h = (const float*)d_in[0];
    const float* w = (const float*)d_in[1];
    const int* tg = (const int*)d_in[2];
    float* out = (float*)d_out;
    (void)in_sizes; (void)n_in; (void)out_size;

    k_zero<<<(NCHUNK * NBINS + 255) / 256, 256>>>();
    k_prep_w<<<VOCAB, 256>>>(w);
    k_prep_h<<<N_ROWS, 256>>>(h);
    k_pos<<<N_ROWS, 256>>>(h, w, tg);
    k_scan<<<dim3((VOCAB + 255) / 256, 4), 256>>>();
    k_thresh<<<NCHUNK, 256>>>();
    k_collect<<<dim3((VOCAB + 255) / 256, NCHUNK), 256>>>();
    k_main<<<dim3(NCAND / TM, NCHUNK), 256>>>(tg);
    k_final<<<1, 256>>>(out);
}

// round 9
// speedup vs baseline: 3.9029x; 1.0784x over previous
#include <cuda_runtime.h>
#include <cuda_bf16.h>
#include <cstdint>

#define N_ROWS 4096
#define DIM    1024
#define VOCAB  50257
#define LR     64
#define NCAND  2048
#define CH     32
#define NCHUNK 128
#define NBINS  4096
#define LSCALE 20.0f
#define AUXW   0.2f
#define TM     128   // candidates per block (MMA M)
#define KSTEP  64    // K elements per smem stage (128 bytes bf16)
#define NSTAGE (DIM / KSTEP)

// ---------------- persistent device scratch (static, no allocation) -------------
__device__ __nv_bfloat16 g_W[(size_t)VOCAB * DIM];   // raw embedding, bf16 (103MB)
__device__ float g_winv[VOCAB];                      // 1/||W_row||_full
__device__ float g_wlinv[VOCAB];                     // 1/||W_row[:64]||
__device__ __nv_bfloat16 g_H[(size_t)N_ROWS * DIM];  // normalized hidden, bf16
__device__ float g_hinv[N_ROWS];
__device__ float g_hmean[NCHUNK * LR];
__device__ float g_scan[(size_t)NCHUNK * VOCAB];     // 25.7MB, layout [chunk][vocab]
__device__ int   g_hist[NCHUNK * NBINS];
__device__ int   g_thr[NCHUNK];
__device__ int   g_above[NCHUNK];
__device__ int   g_cntA[NCHUNK];
__device__ int   g_cntB[NCHUNK];
__device__ int   g_cand[NCHUNK * NCAND];
__device__ float g_posf[N_ROWS];
__device__ float g_posl[N_ROWS];
__device__ float g_sumf[N_ROWS];
__device__ float g_suml[N_ROWS];

// ---------------- helpers -------------------------------------------------------
__device__ __forceinline__ float2 bf2f2(unsigned int u) {
    __nv_bfloat162 h = *reinterpret_cast<__nv_bfloat162*>(&u);
    return __bfloat1622float2(h);
}
__device__ __forceinline__ unsigned int f2bf2u(float a, float b) {
    __nv_bfloat162 h = __floats2bfloat162_rn(a, b);
    return *reinterpret_cast<unsigned int*>(&h);
}
__device__ __forceinline__ int binof(float v) {
    int b = (int)floorf((v + 0.25f) * 8192.0f);
    return b < 0 ? 0 : (b > NBINS - 1 ? NBINS - 1 : b);
}
__device__ __forceinline__ float block_sum_bcast(float v, float* sbuf) {
    int lane = threadIdx.x & 31, wid = threadIdx.x >> 5;
#pragma unroll
    for (int o = 16; o; o >>= 1) v += __shfl_down_sync(0xffffffffu, v, o);
    if (lane == 0) sbuf[wid] = v;
    __syncthreads();
    if (threadIdx.x == 0) {
        float r = sbuf[0];
        int nw = (int)(blockDim.x >> 5);
        for (int i = 1; i < nw; ++i) r += sbuf[i];
        sbuf[32] = r;
    }
    __syncthreads();
    return sbuf[32];
}
__device__ __forceinline__ uint32_t smem_u32(const void* p) {
    uint32_t a;
    asm("{ .reg .u64 t; cvta.to.shared.u64 t, %1; cvt.u32.u64 %0, t; }"
        : "=r"(a) : "l"(p));
    return a;
}
__device__ __forceinline__ uint32_t sw128(uint32_t off) {
    return off ^ ((off >> 3) & 0x70);
}
__device__ __forceinline__ void ldmat4(uint32_t& r0, uint32_t& r1, uint32_t& r2,
                                       uint32_t& r3, uint32_t addr) {
    asm volatile("ldmatrix.sync.aligned.m8n8.x4.shared.b16 {%0,%1,%2,%3}, [%4];"
                 : "=r"(r0), "=r"(r1), "=r"(r2), "=r"(r3) : "r"(addr));
}
__device__ __forceinline__ void mma16816(float* c, const uint32_t* a,
                                         const uint32_t* b) {
    asm volatile(
        "mma.sync.aligned.m16n8k16.row.col.f32.bf16.bf16.f32 "
        "{%0,%1,%2,%3}, {%4,%5,%6,%7}, {%8,%9}, {%0,%1,%2,%3};"
        : "+f"(c[0]), "+f"(c[1]), "+f"(c[2]), "+f"(c[3])
        : "r"(a[0]), "r"(a[1]), "r"(a[2]), "r"(a[3]), "r"(b[0]), "r"(b[1]));
}

// ---------------- kernels -------------------------------------------------------
__global__ void k_zero() {
    int i = blockIdx.x * blockDim.x + threadIdx.x;
    if (i < NCHUNK * NBINS) g_hist[i] = 0;
    if (i < NCHUNK) { g_cntA[i] = 0; g_cntB[i] = 0; }
    if (i < N_ROWS) { g_sumf[i] = 0.f; g_suml[i] = 0.f; }
    if (i < NCHUNK * LR) g_hmean[i] = 0.f;
}

__global__ void __launch_bounds__(256) k_prep_w(const float* __restrict__ W) {
    __shared__ float sbuf[33];
    int v = blockIdx.x;
    int t = threadIdx.x;
    const float4 x = reinterpret_cast<const float4*>(W + (size_t)v * DIM)[t];
    float ss = x.x * x.x + x.y * x.y + x.z * x.z + x.w * x.w;
    float ssl = (t < 16) ? ss : 0.f;
    float tot = block_sum_bcast(ss, sbuf);
    float totl = block_sum_bcast(ssl, sbuf);
    if (t == 0) {
        g_winv[v] = rsqrtf(fmaxf(tot, 1e-24f));
        g_wlinv[v] = rsqrtf(fmaxf(totl, 1e-24f));
    }
    uint2 u;
    u.x = f2bf2u(x.x, x.y);
    u.y = f2bf2u(x.z, x.w);
    *reinterpret_cast<uint2*>(&g_W[(size_t)v * DIM + 4 * t]) = u;
}

__global__ void __launch_bounds__(256) k_prep_h(const float* __restrict__ H) {
    __shared__ float sbuf[33];
    int r = blockIdx.x;
    int t = threadIdx.x;
    const float4 x = reinterpret_cast<const float4*>(H + (size_t)r * DIM)[t];
    float ss = x.x * x.x + x.y * x.y + x.z * x.z + x.w * x.w;
    float tot = block_sum_bcast(ss, sbuf);
    float inv = 1.f / fmaxf(sqrtf(tot), 1e-6f);
    uint2 u;
    u.x = f2bf2u(x.x * inv, x.y * inv);
    u.y = f2bf2u(x.z * inv, x.w * inv);
    *reinterpret_cast<uint2*>(&g_H[(size_t)r * DIM + 4 * t]) = u;
    if (t == 0) g_hinv[r] = inv;
    if (t < 16) {
        int c = r >> 5;
        const float w = inv * (1.f / 32.f);
        atomicAdd(&g_hmean[c * LR + 4 * t + 0], x.x * w);
        atomicAdd(&g_hmean[c * LR + 4 * t + 1], x.y * w);
        atomicAdd(&g_hmean[c * LR + 4 * t + 2], x.z * w);
        atomicAdd(&g_hmean[c * LR + 4 * t + 3], x.w * w);
    }
}

__global__ void __launch_bounds__(256) k_pos(const float* __restrict__ H,
                                             const float* __restrict__ W,
                                             const int* __restrict__ tg) {
    __shared__ float sbuf[33];
    int r = blockIdx.x;
    int t = threadIdx.x;
    int tgt = tg[r];
    const float4 hx = reinterpret_cast<const float4*>(H + (size_t)r * DIM)[t];
    const float4 wx = reinterpret_cast<const float4*>(W + (size_t)tgt * DIM)[t];
    float d = hx.x * wx.x + hx.y * wx.y + hx.z * wx.z + hx.w * wx.w;
    float dl = (t < 16) ? d : 0.f;
    float td = block_sum_bcast(d, sbuf);
    float tdl = block_sum_bcast(dl, sbuf);
    if (t == 0) {
        float hi = g_hinv[r];
        g_posf[r] = td * hi * g_winv[tgt];
        g_posl[r] = tdl * hi * g_wlinv[tgt];
    }
}

// ---- scan: mma.sync GEMM  Wl(128v x 64) @ hmean^T(64 x 128c) + hist ------------
// Block handles 128 vocab rows x all 128 chunks. Warp w: rows [16w,16w+16).
__global__ void __launch_bounds__(256) k_scan() {
    __shared__ __align__(1024) char sraw[32768];
    __nv_bfloat16* shW = reinterpret_cast<__nv_bfloat16*>(sraw);           // 128x64 SW128
    __nv_bfloat16* shH = reinterpret_cast<__nv_bfloat16*>(sraw + 16384);   // 128x64 SW128
    float* buf = reinterpret_cast<float*>(sraw);                           // 64x128 staging

    const int tid = threadIdx.x;
    const int w = tid >> 5, lane = tid & 31;
    const int v0 = blockIdx.x * 128;

    // load W rows (first 64 cols = 128B/row), zero-pad past VOCAB
#pragma unroll
    for (int r = 0; r < 4; ++r) {
        int i = tid + 256 * r;
        int row = i >> 3, seg = i & 7;
        int v = v0 + row;
        uint4 val = make_uint4(0u, 0u, 0u, 0u);
        if (v < VOCAB)
            val = *reinterpret_cast<const uint4*>(g_W + (size_t)v * DIM + seg * 8);
        *reinterpret_cast<uint4*>(sraw + sw128((uint32_t)(row * 128 + seg * 16))) = val;
    }
    // load hmean (f32 -> bf16): 128 chunks x 64
#pragma unroll
    for (int r = 0; r < 8; ++r) {
        int i = tid + 256 * r;          // 4-elem group id
        int row = i >> 4, seg4 = i & 15;
        const float* hm = &g_hmean[row * LR + seg4 * 4];
        uint2 u;
        u.x = f2bf2u(hm[0], hm[1]);
        u.y = f2bf2u(hm[2], hm[3]);
        *reinterpret_cast<uint2*>(sraw + 16384 +
                                  sw128((uint32_t)(row * 128 + seg4 * 8))) = u;
    }
    __syncthreads();

    float acc[16][4] = {};
    uint32_t baseA = smem_u32(shW), baseB = smem_u32(shH);
#pragma unroll
    for (int kk = 0; kk < 4; ++kk) {
        uint32_t a[4];
        {
            int row = 16 * w + (lane & 15);
            int byteo = kk * 32 + ((lane & 16) ? 16 : 0);
            ldmat4(a[0], a[1], a[2], a[3],
                   baseA + sw128((uint32_t)(row * 128 + byteo)));
        }
        uint32_t b[32];
#pragma unroll
        for (int p = 0; p < 8; ++p) {
            int row = p * 16 + (lane & 7) + ((lane & 16) ? 8 : 0);
            int byteo = kk * 32 + ((lane & 8) ? 16 : 0);
            ldmat4(b[p * 4 + 0], b[p * 4 + 1], b[p * 4 + 2], b[p * 4 + 3],
                   baseB + sw128((uint32_t)(row * 128 + byteo)));
        }
#pragma unroll
        for (int t = 0; t < 16; ++t) mma16816(acc[t], a, &b[t * 2]);
    }

    const int mq = 16 * w + (lane >> 2);
    const float wl0 = (v0 + mq < VOCAB) ? g_wlinv[v0 + mq] : 0.f;
    const float wl1 = (v0 + mq + 8 < VOCAB) ? g_wlinv[v0 + mq + 8] : 0.f;

#pragma unroll
    for (int half = 0; half < 2; ++half) {
        __syncthreads();  // ldmatrix reads / previous dump complete before overwrite
#pragma unroll
        for (int t = half * 8; t < half * 8 + 8; ++t) {
            int n0 = 8 * t + 2 * (lane & 3);
            int nl = n0 - half * 64;
            buf[nl * 128 + (mq ^ (n0 & 31))] = acc[t][0] * wl0;
            buf[(nl + 1) * 128 + (mq ^ ((n0 + 1) & 31))] = acc[t][1] * wl0;
            buf[nl * 128 + ((mq + 8) ^ (n0 & 31))] = acc[t][2] * wl1;
            buf[(nl + 1) * 128 + ((mq + 8) ^ ((n0 + 1) & 31))] = acc[t][3] * wl1;
        }
        __syncthreads();
        // coalesced dump + histogram
        for (int it = 0; it < 32; ++it) {
            int idx = it * 256 + tid;
            int cl = idx >> 7, m = idx & 127;
            int c = half * 64 + cl;
            float val = buf[cl * 128 + (m ^ (c & 31))];
            int v = v0 + m;
            if (v < VOCAB) {
                g_scan[(size_t)c * VOCAB + v] = val;
                atomicAdd(&g_hist[c * NBINS + binof(val)], 1);
            }
        }
    }
}

__global__ void __launch_bounds__(256) k_thresh() {
    __shared__ int part[256];
    int c = blockIdx.x;
    int t = threadIdx.x;
    int s = 0;
    for (int b = t * 16; b < t * 16 + 16; ++b) s += g_hist[c * NBINS + b];
    part[t] = s;
    __syncthreads();
    if (t == 0) {
        int cum = 0, T = 0, above = 0;
        for (int p = 255; p >= 0; --p) {
            if (cum + part[p] >= NCAND) {
                int c2 = cum;
                for (int b = p * 16 + 15; b >= p * 16; --b) {
                    int h = g_hist[c * NBINS + b];
                    if (c2 + h >= NCAND) { T = b; above = c2; break; }
                    c2 += h;
                }
                break;
            }
            cum += part[p];
        }
        g_thr[c] = T;
        g_above[c] = above;
    }
}

__global__ void __launch_bounds__(256) k_collect() {
    int v = blockIdx.x * 256 + threadIdx.x;
    int c = blockIdx.y;
    if (v >= VOCAB) return;
    float val = g_scan[(size_t)c * VOCAB + v];
    int b = binof(val);
    int T = g_thr[c];
    if (b > T) {
        int p = atomicAdd(&g_cntA[c], 1);
        if (p < NCAND) g_cand[c * NCAND + p] = v;
    } else if (b == T) {
        int above = g_above[c];
        int need = NCAND - above;
        int j = atomicAdd(&g_cntB[c], 1);
        if (j < need) g_cand[c * NCAND + above + j] = v;
    }
}

// -------- main GEMM: mma.sync bf16, M=128 cand x N=32 rows x K=1024 -------------
__global__ void __launch_bounds__(256) k_main(const int* __restrict__ tg) {
    __shared__ __align__(1024) __nv_bfloat16 shA[2][TM * KSTEP];  // 2 x 16KB
    __shared__ __align__(1024) __nv_bfloat16 shB[2][CH * KSTEP];  // 2 x 4KB
    __shared__ int sc[TM];
    __shared__ float swf[TM], swl[TM];
    __shared__ int stgt[CH];
    __shared__ float sredF[CH], sredL[CH];

    const int tid = threadIdx.x;
    const int chunk = blockIdx.y;
    const int nb = blockIdx.x;
    const int w = tid >> 5, lane = tid & 31;

    if (tid < TM) {
        int cid = g_cand[chunk * NCAND + nb * TM + tid];
        sc[tid] = cid;
        swf[tid] = g_winv[cid];
        swl[tid] = g_wlinv[cid];
    } else if (tid < TM + CH) {
        int r = tid - TM;
        stgt[r] = tg[chunk * CH + r];
        sredF[r] = 0.f;
        sredL[r] = 0.f;
    }
    __syncthreads();

    const size_t hbase = (size_t)(chunk * CH) * DIM;
    uint4 pa[4];
    uint4 pb;

    auto PF = [&](int s) {
        int k0 = s * KSTEP;
#pragma unroll
        for (int r = 0; r < 4; ++r) {
            int i = tid + 256 * r;
            int row = i >> 3, seg = i & 7;
            pa[r] = *reinterpret_cast<const uint4*>(
                g_W + (size_t)sc[row] * DIM + k0 + seg * 8);
        }
        {
            int row = tid >> 3, seg = tid & 7;
            pb = *reinterpret_cast<const uint4*>(
                g_H + hbase + (size_t)row * DIM + k0 + seg * 8);
        }
    };
    auto ST = [&](int s) {
        char* A = (char*)shA[s & 1];
        char* B = (char*)shB[s & 1];
#pragma unroll
        for (int r = 0; r < 4; ++r) {
            int i = tid + 256 * r;
            int row = i >> 3, seg = i & 7;
            *reinterpret_cast<uint4*>(A + sw128((uint32_t)(row * 128 + seg * 16))) = pa[r];
        }
        {
            int row = tid >> 3, seg = tid & 7;
            *reinterpret_cast<uint4*>(B + sw128((uint32_t)(row * 128 + seg * 16))) = pb;
        }
    };

    float accF[4][4] = {};
    float accL[4][4] = {};

    auto CMP = [&](int s) {
        uint32_t baseA = smem_u32(shA[s & 1]);
        uint32_t baseB = smem_u32(shB[s & 1]);
#pragma unroll
        for (int kk = 0; kk < 4; ++kk) {
            uint32_t a[4];
            {
                int row = 16 * w + (lane & 15);
                int byteo = kk * 32 + ((lane & 16) ? 16 : 0);
                ldmat4(a[0], a[1], a[2], a[3],
                       baseA + sw128((uint32_t)(row * 128 + byteo)));
            }
            uint32_t b[8];
#pragma unroll
            for (int p = 0; p < 2; ++p) {
                int row = p * 16 + (lane & 7) + ((lane & 16) ? 8 : 0);
                int byteo = kk * 32 + ((lane & 8) ? 16 : 0);
                ldmat4(b[p * 4 + 0], b[p * 4 + 1], b[p * 4 + 2], b[p * 4 + 3],
                       baseB + sw128((uint32_t)(row * 128 + byteo)));
            }
#pragma unroll
            for (int t4 = 0; t4 < 4; ++t4) mma16816(accF[t4], a, &b[t4 * 2]);
            if (s == 0) {
#pragma unroll
                for (int t4 = 0; t4 < 4; ++t4) mma16816(accL[t4], a, &b[t4 * 2]);
            }
        }
    };

    PF(0);
    ST(0);
    __syncthreads();
    for (int s = 0; s < NSTAGE; ++s) {
        if (s < NSTAGE - 1) PF(s + 1);
        CMP(s);
        __syncthreads();
        if (s < NSTAGE - 1) {
            ST(s + 1);
            __syncthreads();
        }
    }

    // epilogue: mask -> exp -> reduce over M (xor-shuffle) -> smem atomics
    {
        int m0 = 16 * w + (lane >> 2), m1 = m0 + 8;
        int c0id = sc[m0], c1id = sc[m1];
        float if0 = swf[m0], if1 = swf[m1];
        float il0 = swl[m0], il1 = swl[m1];
#pragma unroll
        for (int t4 = 0; t4 < 4; ++t4) {
            int n0 = t4 * 8 + 2 * (lane & 3);
            int t0 = stgt[n0], t1 = stgt[n0 + 1];
            float v0 = ((c0id == t0) ? 0.f : __expf(LSCALE * accF[t4][0] * if0)) +
                       ((c1id == t0) ? 0.f : __expf(LSCALE * accF[t4][2] * if1));
            float v1 = ((c0id == t1) ? 0.f : __expf(LSCALE * accF[t4][1] * if0)) +
                       ((c1id == t1) ? 0.f : __expf(LSCALE * accF[t4][3] * if1));
            float l0 = ((c0id == t0) ? 0.f : __expf(LSCALE * accL[t4][0] * il0)) +
                       ((c1id == t0) ? 0.f : __expf(LSCALE * accL[t4][2] * il1));
            float l1 = ((c0id == t1) ? 0.f : __expf(LSCALE * accL[t4][1] * il0)) +
                       ((c1id == t1) ? 0.f : __expf(LSCALE * accL[t4][3] * il1));
#pragma unroll
            for (int o = 4; o < 32; o <<= 1) {
                v0 += __shfl_xor_sync(0xffffffffu, v0, o);
                v1 += __shfl_xor_sync(0xffffffffu, v1, o);
                l0 += __shfl_xor_sync(0xffffffffu, l0, o);
                l1 += __shfl_xor_sync(0xffffffffu, l1, o);
            }
            if (lane < 4) {
                atomicAdd(&sredF[n0], v0);
                atomicAdd(&sredF[n0 + 1], v1);
                atomicAdd(&sredL[n0], l0);
                atomicAdd(&sredL[n0 + 1], l1);
            }
        }
    }
    __syncthreads();
    if (tid < CH) {
        atomicAdd(&g_sumf[chunk * CH + tid], sredF[tid]);
        atomicAdd(&g_suml[chunk * CH + tid], sredL[tid]);
    }
}

__global__ void __launch_bounds__(256) k_final(float* __restrict__ out) {
    __shared__ float sbuf[33];
    float acc = 0.f;
    for (int i = threadIdx.x; i < N_ROWS; i += 256) {
        float pf = g_posf[i], pl = g_posl[i];
        float lf = logf(__expf(LSCALE * pf) + g_sumf[i]) - LSCALE * pf;
        float ll = logf(__expf(LSCALE * pl) + g_suml[i]) - LSCALE * pl;
        acc += lf + AUXW * ll;
    }
    float tot = block_sum_bcast(acc, sbuf);
    if (threadIdx.x == 0) out[0] = tot * (1.0f / (float)N_ROWS);
}

// ---------------- launch --------------------------------------------------------
extern "C" void kernel_launch(void* const* d_in, const int* in_sizes, int n_in,
                              void* d_out, int out_size) {
    const float* h = (const float*)d_in[0];
    const float* w = (const float*)d_in[1];
    const int* tg = (const int*)d_in[2];
    float* out = (float*)d_out;
    (void)in_sizes; (void)n_in; (void)out_size;

    k_zero<<<(NCHUNK * NBINS + 255) / 256, 256>>>();
    k_prep_w<<<VOCAB, 256>>>(w);
    k_prep_h<<<N_ROWS, 256>>>(h);
    k_pos<<<N_ROWS, 256>>>(h, w, tg);
    k_scan<<<(VOCAB + 127) / 128, 256>>>();
    k_thresh<<<NCHUNK, 256>>>();
    k_collect<<<dim3((VOCAB + 255) / 256, NCHUNK), 256>>>();
    k_main<<<dim3(NCAND / TM, NCHUNK), 256>>>(tg);
    k_final<<<1, 256>>>(out);
}

// round 10
// speedup vs baseline: 3.9541x; 1.0131x over previous
#include <cuda_runtime.h>
#include <cuda_bf16.h>
#include <cstdint>

#define N_ROWS 4096
#define DIM    1024
#define VOCAB  50257
#define LR     64
#define NCAND  2048
#define CH     32
#define NCHUNK 128
#define NBINS  4096
#define LSCALE 20.0f
#define AUXW   0.2f
#define TM     128   // candidates per block (MMA M)
#define KSTEP  64    // K elements per smem stage (128 bytes bf16)
#define NSTAGE (DIM / KSTEP)
#define PIPE   4     // cp.async pipeline depth
#define STG_BYTES 20480  // 16KB A + 4KB B per stage

// ---------------- persistent device scratch (static, no allocation) -------------
__device__ __nv_bfloat16 g_W[(size_t)VOCAB * DIM];   // raw embedding, bf16 (103MB)
__device__ float g_winv[VOCAB];
__device__ float g_wlinv[VOCAB];
__device__ __nv_bfloat16 g_H[(size_t)N_ROWS * DIM];  // normalized hidden, bf16
__device__ float g_hinv[N_ROWS];
__device__ float g_hmean[NCHUNK * LR];
__device__ float g_scan[(size_t)NCHUNK * VOCAB];     // 25.7MB
__device__ int   g_hist[NCHUNK * NBINS];
__device__ int   g_thr[NCHUNK];
__device__ int   g_above[NCHUNK];
__device__ int   g_cntA[NCHUNK];
__device__ int   g_cntB[NCHUNK];
__device__ int   g_cand[NCHUNK * NCAND];
__device__ float g_posf[N_ROWS];
__device__ float g_posl[N_ROWS];
__device__ float g_sumf[N_ROWS];
__device__ float g_suml[N_ROWS];

// ---------------- helpers -------------------------------------------------------
__device__ __forceinline__ float2 bf2f2(unsigned int u) {
    __nv_bfloat162 h = *reinterpret_cast<__nv_bfloat162*>(&u);
    return __bfloat1622float2(h);
}
__device__ __forceinline__ unsigned int f2bf2u(float a, float b) {
    __nv_bfloat162 h = __floats2bfloat162_rn(a, b);
    return *reinterpret_cast<unsigned int*>(&h);
}
__device__ __forceinline__ int binof(float v) {
    int b = (int)floorf((v + 0.25f) * 8192.0f);
    return b < 0 ? 0 : (b > NBINS - 1 ? NBINS - 1 : b);
}
__device__ __forceinline__ float block_sum_bcast(float v, float* sbuf) {
    int lane = threadIdx.x & 31, wid = threadIdx.x >> 5;
#pragma unroll
    for (int o = 16; o; o >>= 1) v += __shfl_down_sync(0xffffffffu, v, o);
    if (lane == 0) sbuf[wid] = v;
    __syncthreads();
    if (threadIdx.x == 0) {
        float r = sbuf[0];
        int nw = (int)(blockDim.x >> 5);
        for (int i = 1; i < nw; ++i) r += sbuf[i];
        sbuf[32] = r;
    }
    __syncthreads();
    return sbuf[32];
}
__device__ __forceinline__ uint32_t smem_u32(const void* p) {
    uint32_t a;
    asm("{ .reg .u64 t; cvta.to.shared.u64 t, %1; cvt.u32.u64 %0, t; }"
        : "=r"(a) : "l"(p));
    return a;
}
__device__ __forceinline__ uint32_t sw128(uint32_t off) {
    return off ^ ((off >> 3) & 0x70);
}
__device__ __forceinline__ void ldmat4(uint32_t& r0, uint32_t& r1, uint32_t& r2,
                                       uint32_t& r3, uint32_t addr) {
    asm volatile("ldmatrix.sync.aligned.m8n8.x4.shared.b16 {%0,%1,%2,%3}, [%4];"
                 : "=r"(r0), "=r"(r1), "=r"(r2), "=r"(r3) : "r"(addr));
}
__device__ __forceinline__ void mma16816(float* c, const uint32_t* a,
                                         const uint32_t* b) {
    asm volatile(
        "mma.sync.aligned.m16n8k16.row.col.f32.bf16.bf16.f32 "
        "{%0,%1,%2,%3}, {%4,%5,%6,%7}, {%8,%9}, {%0,%1,%2,%3};"
        : "+f"(c[0]), "+f"(c[1]), "+f"(c[2]), "+f"(c[3])
        : "r"(a[0]), "r"(a[1]), "r"(a[2]), "r"(a[3]), "r"(b[0]), "r"(b[1]));
}
__device__ __forceinline__ void cpasync16(uint32_t saddr, const void* gaddr) {
    asm volatile("cp.async.cg.shared.global [%0], [%1], 16;"
                 :: "r"(saddr), "l"(gaddr) : "memory");
}
__device__ __forceinline__ void cp_commit() {
    asm volatile("cp.async.commit_group;" ::: "memory");
}
template <int N>
__device__ __forceinline__ void cp_wait() {
    asm volatile("cp.async.wait_group %0;" :: "n"(N) : "memory");
}

// ---------------- kernels -------------------------------------------------------
__global__ void k_zero() {
    int i = blockIdx.x * blockDim.x + threadIdx.x;
    if (i < NCHUNK * NBINS) g_hist[i] = 0;
    if (i < NCHUNK) { g_cntA[i] = 0; g_cntB[i] = 0; }
    if (i < N_ROWS) { g_sumf[i] = 0.f; g_suml[i] = 0.f; }
    if (i < NCHUNK * LR) g_hmean[i] = 0.f;
}

__global__ void __launch_bounds__(256) k_prep_w(const float* __restrict__ W) {
    __shared__ float sbuf[33];
    int v = blockIdx.x;
    int t = threadIdx.x;
    const float4 x = reinterpret_cast<const float4*>(W + (size_t)v * DIM)[t];
    float ss = x.x * x.x + x.y * x.y + x.z * x.z + x.w * x.w;
    float ssl = (t < 16) ? ss : 0.f;
    float tot = block_sum_bcast(ss, sbuf);
    float totl = block_sum_bcast(ssl, sbuf);
    if (t == 0) {
        g_winv[v] = rsqrtf(fmaxf(tot, 1e-24f));
        g_wlinv[v] = rsqrtf(fmaxf(totl, 1e-24f));
    }
    uint2 u;
    u.x = f2bf2u(x.x, x.y);
    u.y = f2bf2u(x.z, x.w);
    *reinterpret_cast<uint2*>(&g_W[(size_t)v * DIM + 4 * t]) = u;
}

__global__ void __launch_bounds__(256) k_prep_h(const float* __restrict__ H) {
    __shared__ float sbuf[33];
    int r = blockIdx.x;
    int t = threadIdx.x;
    const float4 x = reinterpret_cast<const float4*>(H + (size_t)r * DIM)[t];
    float ss = x.x * x.x + x.y * x.y + x.z * x.z + x.w * x.w;
    float tot = block_sum_bcast(ss, sbuf);
    float inv = 1.f / fmaxf(sqrtf(tot), 1e-6f);
    uint2 u;
    u.x = f2bf2u(x.x * inv, x.y * inv);
    u.y = f2bf2u(x.z * inv, x.w * inv);
    *reinterpret_cast<uint2*>(&g_H[(size_t)r * DIM + 4 * t]) = u;
    if (t == 0) g_hinv[r] = inv;
    if (t < 16) {
        int c = r >> 5;
        const float w = inv * (1.f / 32.f);
        atomicAdd(&g_hmean[c * LR + 4 * t + 0], x.x * w);
        atomicAdd(&g_hmean[c * LR + 4 * t + 1], x.y * w);
        atomicAdd(&g_hmean[c * LR + 4 * t + 2], x.z * w);
        atomicAdd(&g_hmean[c * LR + 4 * t + 3], x.w * w);
    }
}

__global__ void __launch_bounds__(256) k_pos(const float* __restrict__ H,
                                             const float* __restrict__ W,
                                             const int* __restrict__ tg) {
    __shared__ float sbuf[33];
    int r = blockIdx.x;
    int t = threadIdx.x;
    int tgt = tg[r];
    const float4 hx = reinterpret_cast<const float4*>(H + (size_t)r * DIM)[t];
    const float4 wx = reinterpret_cast<const float4*>(W + (size_t)tgt * DIM)[t];
    float d = hx.x * wx.x + hx.y * wx.y + hx.z * wx.z + hx.w * wx.w;
    float dl = (t < 16) ? d : 0.f;
    float td = block_sum_bcast(d, sbuf);
    float tdl = block_sum_bcast(dl, sbuf);
    if (t == 0) {
        float hi = g_hinv[r];
        g_posf[r] = td * hi * g_winv[tgt];
        g_posl[r] = tdl * hi * g_wlinv[tgt];
    }
}

// ---- scan: mma.sync GEMM  Wl(128v x 64) @ hmean^T(64 x 128c) + hist ------------
__global__ void __launch_bounds__(256) k_scan() {
    __shared__ __align__(1024) char sraw[32768];
    __nv_bfloat16* shW = reinterpret_cast<__nv_bfloat16*>(sraw);
    __nv_bfloat16* shH = reinterpret_cast<__nv_bfloat16*>(sraw + 16384);
    float* buf = reinterpret_cast<float*>(sraw);

    const int tid = threadIdx.x;
    const int w = tid >> 5, lane = tid & 31;
    const int v0 = blockIdx.x * 128;

#pragma unroll
    for (int r = 0; r < 4; ++r) {
        int i = tid + 256 * r;
        int row = i >> 3, seg = i & 7;
        int v = v0 + row;
        uint4 val = make_uint4(0u, 0u, 0u, 0u);
        if (v < VOCAB)
            val = *reinterpret_cast<const uint4*>(g_W + (size_t)v * DIM + seg * 8);
        *reinterpret_cast<uint4*>(sraw + sw128((uint32_t)(row * 128 + seg * 16))) = val;
    }
#pragma unroll
    for (int r = 0; r < 8; ++r) {
        int i = tid + 256 * r;
        int row = i >> 4, seg4 = i & 15;
        const float* hm = &g_hmean[row * LR + seg4 * 4];
        uint2 u;
        u.x = f2bf2u(hm[0], hm[1]);
        u.y = f2bf2u(hm[2], hm[3]);
        *reinterpret_cast<uint2*>(sraw + 16384 +
                                  sw128((uint32_t)(row * 128 + seg4 * 8))) = u;
    }
    __syncthreads();

    float acc[16][4] = {};
    uint32_t baseA = smem_u32(shW), baseB = smem_u32(shH);
#pragma unroll
    for (int kk = 0; kk < 4; ++kk) {
        uint32_t a[4];
        {
            int row = 16 * w + (lane & 15);
            int byteo = kk * 32 + ((lane & 16) ? 16 : 0);
            ldmat4(a[0], a[1], a[2], a[3],
                   baseA + sw128((uint32_t)(row * 128 + byteo)));
        }
        uint32_t b[32];
#pragma unroll
        for (int p = 0; p < 8; ++p) {
            int row = p * 16 + (lane & 7) + ((lane & 16) ? 8 : 0);
            int byteo = kk * 32 + ((lane & 8) ? 16 : 0);
            ldmat4(b[p * 4 + 0], b[p * 4 + 1], b[p * 4 + 2], b[p * 4 + 3],
                   baseB + sw128((uint32_t)(row * 128 + byteo)));
        }
#pragma unroll
        for (int t = 0; t < 16; ++t) mma16816(acc[t], a, &b[t * 2]);
    }

    const int mq = 16 * w + (lane >> 2);
    const float wl0 = (v0 + mq < VOCAB) ? g_wlinv[v0 + mq] : 0.f;
    const float wl1 = (v0 + mq + 8 < VOCAB) ? g_wlinv[v0 + mq + 8] : 0.f;

#pragma unroll
    for (int half = 0; half < 2; ++half) {
        __syncthreads();
#pragma unroll
        for (int t = half * 8; t < half * 8 + 8; ++t) {
            int n0 = 8 * t + 2 * (lane & 3);
            int nl = n0 - half * 64;
            buf[nl * 128 + (mq ^ (n0 & 31))] = acc[t][0] * wl0;
            buf[(nl + 1) * 128 + (mq ^ ((n0 + 1) & 31))] = acc[t][1] * wl0;
            buf[nl * 128 + ((mq + 8) ^ (n0 & 31))] = acc[t][2] * wl1;
            buf[(nl + 1) * 128 + ((mq + 8) ^ ((n0 + 1) & 31))] = acc[t][3] * wl1;
        }
        __syncthreads();
        for (int it = 0; it < 32; ++it) {
            int idx = it * 256 + tid;
            int cl = idx >> 7, m = idx & 127;
            int c = half * 64 + cl;
            float val = buf[cl * 128 + (m ^ (c & 31))];
            int v = v0 + m;
            if (v < VOCAB) {
                g_scan[(size_t)c * VOCAB + v] = val;
                atomicAdd(&g_hist[c * NBINS + binof(val)], 1);
            }
        }
    }
}

__global__ void __launch_bounds__(256) k_thresh() {
    __shared__ int part[256];
    int c = blockIdx.x;
    int t = threadIdx.x;
    int s = 0;
    for (int b = t * 16; b < t * 16 + 16; ++b) s += g_hist[c * NBINS + b];
    part[t] = s;
    __syncthreads();
    if (t == 0) {
        int cum = 0, T = 0, above = 0;
        for (int p = 255; p >= 0; --p) {
            if (cum + part[p] >= NCAND) {
                int c2 = cum;
                for (int b = p * 16 + 15; b >= p * 16; --b) {
                    int h = g_hist[c * NBINS + b];
                    if (c2 + h >= NCAND) { T = b; above = c2; break; }
                    c2 += h;
                }
                break;
            }
            cum += part[p];
        }
        g_thr[c] = T;
        g_above[c] = above;
    }
}

__global__ void __launch_bounds__(256) k_collect() {
    int v = blockIdx.x * 256 + threadIdx.x;
    int c = blockIdx.y;
    if (v >= VOCAB) return;
    float val = g_scan[(size_t)c * VOCAB + v];
    int b = binof(val);
    int T = g_thr[c];
    if (b > T) {
        int p = atomicAdd(&g_cntA[c], 1);
        if (p < NCAND) g_cand[c * NCAND + p] = v;
    } else if (b == T) {
        int above = g_above[c];
        int need = NCAND - above;
        int j = atomicAdd(&g_cntB[c], 1);
        if (j < need) g_cand[c * NCAND + above + j] = v;
    }
}

// -------- main GEMM: mma.sync bf16 + 4-stage cp.async pipeline ------------------
__global__ void __launch_bounds__(256) k_main(const int* __restrict__ tg) {
    extern __shared__ __align__(1024) char dyn[];   // PIPE * STG_BYTES
    __shared__ int sc[TM];
    __shared__ float swf[TM], swl[TM];
    __shared__ int stgt[CH];
    __shared__ float sredF[CH], sredL[CH];

    const int tid = threadIdx.x;
    const int chunk = blockIdx.y;
    const int nb = blockIdx.x;
    const int w = tid >> 5, lane = tid & 31;

    if (tid < TM) {
        int cid = g_cand[chunk * NCAND + nb * TM + tid];
        sc[tid] = cid;
        swf[tid] = g_winv[cid];
        swl[tid] = g_wlinv[cid];
    } else if (tid < TM + CH) {
        int r = tid - TM;
        stgt[r] = tg[chunk * CH + r];
        sredF[r] = 0.f;
        sredL[r] = 0.f;
    }
    __syncthreads();

    const size_t hbase = (size_t)(chunk * CH) * DIM;
    // per-thread fixed roles for the fill
    const int arow[4] = {(tid + 0) >> 3, (tid + 256) >> 3, (tid + 512) >> 3,
                         (tid + 768) >> 3};
    const int aseg = tid & 7;
    const int brow = tid >> 3, bseg = tid & 7;

    auto ISSUE = [&](int s) {
        char* base = dyn + (s & (PIPE - 1)) * STG_BYTES;
        uint32_t sb = smem_u32(base);
        int k0 = s * KSTEP;
#pragma unroll
        for (int r = 0; r < 4; ++r) {
            cpasync16(sb + sw128((uint32_t)(arow[r] * 128 + aseg * 16)),
                      g_W + (size_t)sc[arow[r]] * DIM + k0 + aseg * 8);
        }
        cpasync16(sb + 16384 + sw128((uint32_t)(brow * 128 + bseg * 16)),
                  g_H + hbase + (size_t)brow * DIM + k0 + bseg * 8);
        cp_commit();
    };

    float accF[4][4] = {};
    float accL[4][4] = {};

    auto CMP = [&](int s) {
        char* base = dyn + (s & (PIPE - 1)) * STG_BYTES;
        uint32_t baseA = smem_u32(base);
        uint32_t baseB = baseA + 16384;
#pragma unroll
        for (int kk = 0; kk < 4; ++kk) {
            uint32_t a[4];
            {
                int row = 16 * w + (lane & 15);
                int byteo = kk * 32 + ((lane & 16) ? 16 : 0);
                ldmat4(a[0], a[1], a[2], a[3],
                       baseA + sw128((uint32_t)(row * 128 + byteo)));
            }
            uint32_t b[8];
#pragma unroll
            for (int p = 0; p < 2; ++p) {
                int row = p * 16 + (lane & 7) + ((lane & 16) ? 8 : 0);
                int byteo = kk * 32 + ((lane & 8) ? 16 : 0);
                ldmat4(b[p * 4 + 0], b[p * 4 + 1], b[p * 4 + 2], b[p * 4 + 3],
                       baseB + sw128((uint32_t)(row * 128 + byteo)));
            }
#pragma unroll
            for (int t4 = 0; t4 < 4; ++t4) mma16816(accF[t4], a, &b[t4 * 2]);
            if (s == 0) {
#pragma unroll
                for (int t4 = 0; t4 < 4; ++t4) mma16816(accL[t4], a, &b[t4 * 2]);
            }
        }
    };

    // prologue: stages 0..PIPE-2 in flight
#pragma unroll
    for (int s = 0; s < PIPE - 1; ++s) ISSUE(s);

    for (int s = 0; s < NSTAGE; ++s) {
        cp_wait<PIPE - 2>();       // stage s landed
        __syncthreads();           // all warps past CMP(s-1); buffer (s-1)&3 free
        if (s + PIPE - 1 < NSTAGE) ISSUE(s + PIPE - 1);
        CMP(s);
    }

    // epilogue: mask -> exp -> reduce over M (xor-shuffle) -> smem atomics
    {
        int m0 = 16 * w + (lane >> 2), m1 = m0 + 8;
        int c0id = sc[m0], c1id = sc[m1];
        float if0 = swf[m0], if1 = swf[m1];
        float il0 = swl[m0], il1 = swl[m1];
#pragma unroll
        for (int t4 = 0; t4 < 4; ++t4) {
            int n0 = t4 * 8 + 2 * (lane & 3);
            int t0 = stgt[n0], t1 = stgt[n0 + 1];
            float v0 = ((c0id == t0) ? 0.f : __expf(LSCALE * accF[t4][0] * if0)) +
                       ((c1id == t0) ? 0.f : __expf(LSCALE * accF[t4][2] * if1));
            float v1 = ((c0id == t1) ? 0.f : __expf(LSCALE * accF[t4][1] * if0)) +
                       ((c1id == t1) ? 0.f : __expf(LSCALE * accF[t4][3] * if1));
            float l0 = ((c0id == t0) ? 0.f : __expf(LSCALE * accL[t4][0] * il0)) +
                       ((c1id == t0) ? 0.f : __expf(LSCALE * accL[t4][2] * il1));
            float l1 = ((c0id == t1) ? 0.f : __expf(LSCALE * accL[t4][1] * il0)) +
                       ((c1id == t1) ? 0.f : __expf(LSCALE * accL[t4][3] * il1));
#pragma unroll
            for (int o = 4; o < 32; o <<= 1) {
                v0 += __shfl_xor_sync(0xffffffffu, v0, o);
                v1 += __shfl_xor_sync(0xffffffffu, v1, o);
                l0 += __shfl_xor_sync(0xffffffffu, l0, o);
                l1 += __shfl_xor_sync(0xffffffffu, l1, o);
            }
            if (lane < 4) {
                atomicAdd(&sredF[n0], v0);
                atomicAdd(&sredF[n0 + 1], v1);
                atomicAdd(&sredL[n0], l0);
                atomicAdd(&sredL[n0 + 1], l1);
            }
        }
    }
    __syncthreads();
    if (tid < CH) {
        atomicAdd(&g_sumf[chunk * CH + tid], sredF[tid]);
        atomicAdd(&g_suml[chunk * CH + tid], sredL[tid]);
    }
}

__global__ void __launch_bounds__(256) k_final(float* __restrict__ out) {
    __shared__ float sbuf[33];
    float acc = 0.f;
    for (int i = threadIdx.x; i < N_ROWS; i += 256) {
        float pf = g_posf[i], pl = g_posl[i];
        float lf = logf(__expf(LSCALE * pf) + g_sumf[i]) - LSCALE * pf;
        float ll = logf(__expf(LSCALE * pl) + g_suml[i]) - LSCALE * pl;
        acc += lf + AUXW * ll;
    }
    float tot = block_sum_bcast(acc, sbuf);
    if (threadIdx.x == 0) out[0] = tot * (1.0f / (float)N_ROWS);
}

// ---------------- launch --------------------------------------------------------
extern "C" void kernel_launch(void* const* d_in, const int* in_sizes, int n_in,
                              void* d_out, int out_size) {
    const float* h = (const float*)d_in[0];
    const float* w = (const float*)d_in[1];
    const int* tg = (const int*)d_in[2];
    float* out = (float*)d_out;
    (void)in_sizes; (void)n_in; (void)out_size;

    cudaFuncSetAttribute(k_main, cudaFuncAttributeMaxDynamicSharedMemorySize,
                         PIPE * STG_BYTES);

    k_zero<<<(NCHUNK * NBINS + 255) / 256, 256>>>();
    k_prep_w<<<VOCAB, 256>>>(w);
    k_prep_h<<<N_ROWS, 256>>>(h);
    k_pos<<<N_ROWS, 256>>>(h, w, tg);
    k_scan<<<(VOCAB + 127) / 128, 256>>>();
    k_thresh<<<NCHUNK, 256>>>();
    k_collect<<<dim3((VOCAB + 255) / 256, NCHUNK), 256>>>();
    k_main<<<dim3(NCAND / TM, NCHUNK), 256, PIPE * STG_BYTES>>>(tg);
    k_final<<<1, 256>>>(out);
}

// round 13
// speedup vs baseline: 4.2725x; 1.0805x over previous
#include <cuda_runtime.h>
#include <cuda_bf16.h>
#include <cstdint>

#define N_ROWS 4096
#define DIM    1024
#define VOCAB  50257
#define LR     64
#define NCAND  2048
#define CH     32
#define NCHUNK 128
#define NBINS  4096
#define LSCALE 20.0f
#define AUXW   0.2f
#define TM     128      // candidates per block (MMA M)
#define NST8   8        // fp8 stages: 128 bytes per row per stage
#define PIPE   4
#define STG_BYTES 20480 // 16KB A + 4KB B per stage

// ---------------- persistent device scratch (static, no allocation) -------------
__device__ uint8_t g_W8[(size_t)VOCAB * DIM];        // e4m3(w_raw*winv*16), 51MB
__device__ __nv_bfloat16 g_Wl16[(size_t)VOCAB * LR]; // bf16 raw W, first 64 cols
__device__ uint8_t g_H8[(size_t)N_ROWS * DIM];       // e4m3(h_norm*16)
__device__ float g_winv[VOCAB];
__device__ float g_wlinv[VOCAB];
__device__ float g_hinv[N_ROWS];
__device__ float g_hmean[NCHUNK * LR];
__device__ float g_scan[(size_t)NCHUNK * VOCAB];
__device__ int   g_hist[NCHUNK * NBINS];
__device__ int   g_thr[NCHUNK];
__device__ int   g_above[NCHUNK];
__device__ int   g_cntA[NCHUNK];
__device__ int   g_cntB[NCHUNK];
__device__ int   g_cand[NCHUNK * NCAND];
__device__ float g_posf[N_ROWS];
__device__ float g_posl[N_ROWS];
__device__ float g_sumf[N_ROWS];
__device__ float g_suml[N_ROWS];

// ---------------- helpers -------------------------------------------------------
__device__ __forceinline__ unsigned int f2bf2u(float a, float b) {
    __nv_bfloat162 h = __floats2bfloat162_rn(a, b);
    return *reinterpret_cast<unsigned int*>(&h);
}
// pack 4 floats -> 4 e4m3 bytes (little-endian element order)
__device__ __forceinline__ uint32_t f4_to_e4m3(float x0, float x1, float x2, float x3) {
    unsigned short p01, p23;
    asm("cvt.rn.satfinite.e4m3x2.f32 %0, %1, %2;" : "=h"(p01) : "f"(x1), "f"(x0));
    asm("cvt.rn.satfinite.e4m3x2.f32 %0, %1, %2;" : "=h"(p23) : "f"(x3), "f"(x2));
    return (uint32_t)p01 | ((uint32_t)p23 << 16);
}
__device__ __forceinline__ int binof(float v) {
    int b = (int)floorf((v + 0.25f) * 8192.0f);
    return b < 0 ? 0 : (b > NBINS - 1 ? NBINS - 1 : b);
}
__device__ __forceinline__ float block_sum_bcast(float v, float* sbuf) {
    int lane = threadIdx.x & 31, wid = threadIdx.x >> 5;
#pragma unroll
    for (int o = 16; o; o >>= 1) v += __shfl_down_sync(0xffffffffu, v, o);
    if (lane == 0) sbuf[wid] = v;
    __syncthreads();
    if (threadIdx.x == 0) {
        float r = sbuf[0];
        int nw = (int)(blockDim.x >> 5);
        for (int i = 1; i < nw; ++i) r += sbuf[i];
        sbuf[32] = r;
    }
    __syncthreads();
    return sbuf[32];
}
__device__ __forceinline__ uint32_t smem_u32(const void* p) {
    uint32_t a;
    asm("{ .reg .u64 t; cvta.to.shared.u64 t, %1; cvt.u32.u64 %0, t; }"
        : "=r"(a) : "l"(p));
    return a;
}
__device__ __forceinline__ uint32_t sw128(uint32_t off) {
    return off ^ ((off >> 3) & 0x70);
}
__device__ __forceinline__ void ldmat4(uint32_t& r0, uint32_t& r1, uint32_t& r2,
                                       uint32_t& r3, uint32_t addr) {
    asm volatile("ldmatrix.sync.aligned.m8n8.x4.shared.b16 {%0,%1,%2,%3}, [%4];"
                 : "=r"(r0), "=r"(r1), "=r"(r2), "=r"(r3) : "r"(addr));
}
__device__ __forceinline__ void mma16816(float* c, const uint32_t* a,
                                         const uint32_t* b) {
    asm volatile(
        "mma.sync.aligned.m16n8k16.row.col.f32.bf16.bf16.f32 "
        "{%0,%1,%2,%3}, {%4,%5,%6,%7}, {%8,%9}, {%0,%1,%2,%3};"
        : "+f"(c[0]), "+f"(c[1]), "+f"(c[2]), "+f"(c[3])
        : "r"(a[0]), "r"(a[1]), "r"(a[2]), "r"(a[3]), "r"(b[0]), "r"(b[1]));
}
__device__ __forceinline__ void mma16832f8(float* c, const uint32_t* a,
                                           const uint32_t* b) {
    asm volatile(
        "mma.sync.aligned.m16n8k32.row.col.f32.e4m3.e4m3.f32 "
        "{%0,%1,%2,%3}, {%4,%5,%6,%7}, {%8,%9}, {%0,%1,%2,%3};"
        : "+f"(c[0]), "+f"(c[1]), "+f"(c[2]), "+f"(c[3])
        : "r"(a[0]), "r"(a[1]), "r"(a[2]), "r"(a[3]), "r"(b[0]), "r"(b[1]));
}
__device__ __forceinline__ void cpasync16(uint32_t saddr, const void* gaddr) {
    asm volatile("cp.async.cg.shared.global [%0], [%1], 16;"
                 :: "r"(saddr), "l"(gaddr) : "memory");
}
__device__ __forceinline__ void cp_commit() {
    asm volatile("cp.async.commit_group;" ::: "memory");
}
template <int N>
__device__ __forceinline__ void cp_wait() {
    asm volatile("cp.async.wait_group %0;" :: "n"(N) : "memory");
}

// ---------------- kernels -------------------------------------------------------
__global__ void k_zero() {
    int i = blockIdx.x * blockDim.x + threadIdx.x;
    if (i < NCHUNK * NBINS) g_hist[i] = 0;
    if (i < NCHUNK) { g_cntA[i] = 0; g_cntB[i] = 0; }
    if (i < N_ROWS) { g_sumf[i] = 0.f; g_suml[i] = 0.f; }
    if (i < NCHUNK * LR) g_hmean[i] = 0.f;
}

__global__ void __launch_bounds__(256) k_prep_w(const float* __restrict__ W) {
    __shared__ float sbuf[33];
    int v = blockIdx.x;
    int t = threadIdx.x;
    const float4 x = reinterpret_cast<const float4*>(W + (size_t)v * DIM)[t];
    float ss = x.x * x.x + x.y * x.y + x.z * x.z + x.w * x.w;
    float ssl = (t < 16) ? ss : 0.f;
    float tot = block_sum_bcast(ss, sbuf);
    float totl = block_sum_bcast(ssl, sbuf);
    float inv = rsqrtf(fmaxf(tot, 1e-24f));
    if (t == 0) {
        g_winv[v] = inv;
        g_wlinv[v] = rsqrtf(fmaxf(totl, 1e-24f));
    }
    const float sc = inv * 16.f;
    reinterpret_cast<uint32_t*>(g_W8 + (size_t)v * DIM)[t] =
        f4_to_e4m3(x.x * sc, x.y * sc, x.z * sc, x.w * sc);
    if (t < 16) {
        uint2 u;
        u.x = f2bf2u(x.x, x.y);
        u.y = f2bf2u(x.z, x.w);
        *reinterpret_cast<uint2*>(&g_Wl16[(size_t)v * LR + 4 * t]) = u;
    }
}

__global__ void __launch_bounds__(256) k_prep_h(const float* __restrict__ H) {
    __shared__ float sbuf[33];
    int r = blockIdx.x;
    int t = threadIdx.x;
    const float4 x = reinterpret_cast<const float4*>(H + (size_t)r * DIM)[t];
    float ss = x.x * x.x + x.y * x.y + x.z * x.z + x.w * x.w;
    float tot = block_sum_bcast(ss, sbuf);
    float inv = 1.f / fmaxf(sqrtf(tot), 1e-6f);
    const float sc = inv * 16.f;
    reinterpret_cast<uint32_t*>(g_H8 + (size_t)r * DIM)[t] =
        f4_to_e4m3(x.x * sc, x.y * sc, x.z * sc, x.w * sc);
    if (t == 0) g_hinv[r] = inv;
    if (t < 16) {
        int c = r >> 5;
        const float w = inv * (1.f / 32.f);
        atomicAdd(&g_hmean[c * LR + 4 * t + 0], x.x * w);
        atomicAdd(&g_hmean[c * LR + 4 * t + 1], x.y * w);
        atomicAdd(&g_hmean[c * LR + 4 * t + 2], x.z * w);
        atomicAdd(&g_hmean[c * LR + 4 * t + 3], x.w * w);
    }
}

__global__ void __launch_bounds__(256) k_pos(const float* __restrict__ H,
                                             const float* __restrict__ W,
                                             const int* __restrict__ tg) {
    __shared__ float sbuf[33];
    int r = blockIdx.x;
    int t = threadIdx.x;
    int tgt = tg[r];
    const float4 hx = reinterpret_cast<const float4*>(H + (size_t)r * DIM)[t];
    const float4 wx = reinterpret_cast<const float4*>(W + (size_t)tgt * DIM)[t];
    float d = hx.x * wx.x + hx.y * wx.y + hx.z * wx.z + hx.w * wx.w;
    float dl = (t < 16) ? d : 0.f;
    float td = block_sum_bcast(d, sbuf);
    float tdl = block_sum_bcast(dl, sbuf);
    if (t == 0) {
        float hi = g_hinv[r];
        g_posf[r] = td * hi * g_winv[tgt];
        g_posl[r] = tdl * hi * g_wlinv[tgt];
    }
}

// ---- scan: mma.sync GEMM  Wl(128v x 64) @ hmean^T(64 x 128c) + hist ------------
__global__ void __launch_bounds__(256) k_scan() {
    __shared__ __align__(1024) char sraw[32768];
    float* buf = reinterpret_cast<float*>(sraw);

    const int tid = threadIdx.x;
    const int w = tid >> 5, lane = tid & 31;
    const int v0 = blockIdx.x * 128;

#pragma unroll
    for (int r = 0; r < 4; ++r) {
        int i = tid + 256 * r;
        int row = i >> 3, seg = i & 7;
        int v = v0 + row;
        uint4 val = make_uint4(0u, 0u, 0u, 0u);
        if (v < VOCAB)
            val = *reinterpret_cast<const uint4*>(g_Wl16 + (size_t)v * LR + seg * 8);
        *reinterpret_cast<uint4*>(sraw + sw128((uint32_t)(row * 128 + seg * 16))) = val;
    }
#pragma unroll
    for (int r = 0; r < 8; ++r) {
        int i = tid + 256 * r;
        int row = i >> 4, seg4 = i & 15;
        const float* hm = &g_hmean[row * LR + seg4 * 4];
        uint2 u;
        u.x = f2bf2u(hm[0], hm[1]);
        u.y = f2bf2u(hm[2], hm[3]);
        *reinterpret_cast<uint2*>(sraw + 16384 +
                                  sw128((uint32_t)(row * 128 + seg4 * 8))) = u;
    }
    __syncthreads();

    float acc[16][4] = {};
    uint32_t baseA = smem_u32(sraw), baseB = baseA + 16384;
#pragma unroll
    for (int kk = 0; kk < 4; ++kk) {
        uint32_t a[4];
        {
            int row = 16 * w + (lane & 15);
            int byteo = kk * 32 + ((lane & 16) ? 16 : 0);
            ldmat4(a[0], a[1], a[2], a[3],
                   baseA + sw128((uint32_t)(row * 128 + byteo)));
        }
        uint32_t b[32];
#pragma unroll
        for (int p = 0; p < 8; ++p) {
            int row = p * 16 + (lane & 7) + ((lane & 16) ? 8 : 0);
            int byteo = kk * 32 + ((lane & 8) ? 16 : 0);
            ldmat4(b[p * 4 + 0], b[p * 4 + 1], b[p * 4 + 2], b[p * 4 + 3],
                   baseB + sw128((uint32_t)(row * 128 + byteo)));
        }
#pragma unroll
        for (int t = 0; t < 16; ++t) mma16816(acc[t], a, &b[t * 2]);
    }

    const int mq = 16 * w + (lane >> 2);
    const float wl0 = (v0 + mq < VOCAB) ? g_wlinv[v0 + mq] : 0.f;
    const float wl1 = (v0 + mq + 8 < VOCAB) ? g_wlinv[v0 + mq + 8] : 0.f;

#pragma unroll
    for (int half = 0; half < 2; ++half) {
        __syncthreads();
#pragma unroll
        for (int t = half * 8; t < half * 8 + 8; ++t) {
            int n0 = 8 * t + 2 * (lane & 3);
            int nl = n0 - half * 64;
            buf[nl * 128 + (mq ^ (n0 & 31))] = acc[t][0] * wl0;
            buf[(nl + 1) * 128 + (mq ^ ((n0 + 1) & 31))] = acc[t][1] * wl0;
            buf[nl * 128 + ((mq + 8) ^ (n0 & 31))] = acc[t][2] * wl1;
            buf[(nl + 1) * 128 + ((mq + 8) ^ ((n0 + 1) & 31))] = acc[t][3] * wl1;
        }
        __syncthreads();
        for (int it = 0; it < 32; ++it) {
            int idx = it * 256 + tid;
            int cl = idx >> 7, m = idx & 127;
            int c = half * 64 + cl;
            float val = buf[cl * 128 + (m ^ (c & 31))];
            int v = v0 + m;
            if (v < VOCAB) {
                g_scan[(size_t)c * VOCAB + v] = val;
                atomicAdd(&g_hist[c * NBINS + binof(val)], 1);
            }
        }
    }
}

__global__ void __launch_bounds__(256) k_thresh() {
    __shared__ int part[256];
    int c = blockIdx.x;
    int t = threadIdx.x;
    int s = 0;
    for (int b = t * 16; b < t * 16 + 16; ++b) s += g_hist[c * NBINS + b];
    part[t] = s;
    __syncthreads();
    if (t == 0) {
        int cum = 0, T = 0, above = 0;
        for (int p = 255; p >= 0; --p) {
            if (cum + part[p] >= NCAND) {
                int c2 = cum;
                for (int b = p * 16 + 15; b >= p * 16; --b) {
                    int h = g_hist[c * NBINS + b];
                    if (c2 + h >= NCAND) { T = b; above = c2; break; }
                    c2 += h;
                }
                break;
            }
            cum += part[p];
        }
        g_thr[c] = T;
        g_above[c] = above;
    }
}

__global__ void __launch_bounds__(256) k_collect() {
    int v = blockIdx.x * 256 + threadIdx.x;
    int c = blockIdx.y;
    if (v >= VOCAB) return;
    float val = g_scan[(size_t)c * VOCAB + v];
    int b = binof(val);
    int T = g_thr[c];
    if (b > T) {
        int p = atomicAdd(&g_cntA[c], 1);
        if (p < NCAND) g_cand[c * NCAND + p] = v;
    } else if (b == T) {
        int above = g_above[c];
        int need = NCAND - above;
        int j = atomicAdd(&g_cntB[c], 1);
        if (j < need) g_cand[c * NCAND + above + j] = v;
    }
}

// -------- main GEMM: fp8 mma.sync, M=128 cand x N=32 rows x K=1024 --------------
__global__ void __launch_bounds__(256) k_main(const int* __restrict__ tg) {
    extern __shared__ __align__(1024) char dyn[];   // PIPE * STG_BYTES
    __shared__ int sc[TM];
    __shared__ float swl[TM];
    __shared__ int stgt[CH];
    __shared__ float sredF[CH], sredL[CH];

    const int tid = threadIdx.x;
    const int chunk = blockIdx.y;
    const int nb = blockIdx.x;
    const int w = tid >> 5, lane = tid & 31;

    if (tid < TM) {
        int cid = g_cand[chunk * NCAND + nb * TM + tid];
        sc[tid] = cid;
        swl[tid] = g_wlinv[cid] / (256.f * g_winv[cid]);
    } else if (tid < TM + CH) {
        int r = tid - TM;
        stgt[r] = tg[chunk * CH + r];
        sredF[r] = 0.f;
        sredL[r] = 0.f;
    }
    __syncthreads();

    const size_t hbase = (size_t)(chunk * CH) * DIM;
    const int arow[4] = {(tid + 0) >> 3, (tid + 256) >> 3, (tid + 512) >> 3,
                         (tid + 768) >> 3};
    const int aseg = tid & 7;
    const int brow = tid >> 3, bseg = tid & 7;

    auto ISSUE = [&](int s) {
        char* base = dyn + (s & (PIPE - 1)) * STG_BYTES;
        uint32_t sb = smem_u32(base);
        int k0 = s * 128;                     // byte offset within row
#pragma unroll
        for (int r = 0; r < 4; ++r) {
            cpasync16(sb + sw128((uint32_t)(arow[r] * 128 + aseg * 16)),
                      g_W8 + (size_t)sc[arow[r]] * DIM + k0 + aseg * 16);
        }
        cpasync16(sb + 16384 + sw128((uint32_t)(brow * 128 + bseg * 16)),
                  g_H8 + hbase + (size_t)brow * DIM + k0 + bseg * 16);
        cp_commit();
    };

    float accF[4][4] = {};
    float accL[4][4] = {};

    auto CMP = [&](int s) {
        char* base = dyn + (s & (PIPE - 1)) * STG_BYTES;
        uint32_t baseA = smem_u32(base);
        uint32_t baseB = baseA + 16384;
#pragma unroll
        for (int kk = 0; kk < 4; ++kk) {
            uint32_t a[4];
            {
                int row = 16 * w + (lane & 15);
                int byteo = kk * 32 + ((lane & 16) ? 16 : 0);
                ldmat4(a[0], a[1], a[2], a[3],
                       baseA + sw128((uint32_t)(row * 128 + byteo)));
            }
            uint32_t b[8];
#pragma unroll
            for (int p = 0; p < 2; ++p) {
                int row = p * 16 + (lane & 7) + ((lane & 16) ? 8 : 0);
                int byteo = kk * 32 + ((lane & 8) ? 16 : 0);
                ldmat4(b[p * 4 + 0], b[p * 4 + 1], b[p * 4 + 2], b[p * 4 + 3],
                       baseB + sw128((uint32_t)(row * 128 + byteo)));
            }
#pragma unroll
            for (int t4 = 0; t4 < 4; ++t4) mma16832f8(accF[t4], a, &b[t4 * 2]);
            if (s == 0 && kk < 2) {           // K bytes 0..63 = low-rank prefix
#pragma unroll
                for (int t4 = 0; t4 < 4; ++t4) mma16832f8(accL[t4], a, &b[t4 * 2]);
            }
        }
    };

#pragma unroll
    for (int s = 0; s < PIPE - 1; ++s) ISSUE(s);

    for (int s = 0; s < NST8; ++s) {
        cp_wait<PIPE - 2>();
        __syncthreads();
        if (s + PIPE - 1 < NST8) ISSUE(s + PIPE - 1);
        CMP(s);
    }

    // epilogue
    {
        int m0 = 16 * w + (lane >> 2), m1 = m0 + 8;
        int c0id = sc[m0], c1id = sc[m1];
        const float FS = 1.f / 256.f;
        float il0 = swl[m0], il1 = swl[m1];
#pragma unroll
        for (int t4 = 0; t4 < 4; ++t4) {
            int n0 = t4 * 8 + 2 * (lane & 3);
            int t0 = stgt[n0], t1 = stgt[n0 + 1];
            float v0 = ((c0id == t0) ? 0.f : __expf(LSCALE * accF[t4][0] * FS)) +
                       ((c1id == t0) ? 0.f : __expf(LSCALE * accF[t4][2] * FS));
            float v1 = ((c0id == t1) ? 0.f : __expf(LSCALE * accF[t4][1] * FS)) +
                       ((c1id == t1) ? 0.f : __expf(LSCALE * accF[t4][3] * FS));
            float l0 = ((c0id == t0) ? 0.f : __expf(LSCALE * accL[t4][0] * il0)) +
                       ((c1id == t0) ? 0.f : __expf(LSCALE * accL[t4][2] * il1));
            float l1 = ((c0id == t1) ? 0.f : __expf(LSCALE * accL[t4][1] * il0)) +
                       ((c1id == t1) ? 0.f : __expf(LSCALE * accL[t4][3] * il1));
#pragma unroll
            for (int o = 4; o < 32; o <<= 1) {
                v0 += __shfl_xor_sync(0xffffffffu, v0, o);
                v1 += __shfl_xor_sync(0xffffffffu, v1, o);
                l0 += __shfl_xor_sync(0xffffffffu, l0, o);
                l1 += __shfl_xor_sync(0xffffffffu, l1, o);
            }
            if (lane < 4) {
                atomicAdd(&sredF[n0], v0);
                atomicAdd(&sredF[n0 + 1], v1);
                atomicAdd(&sredL[n0], l0);
                atomicAdd(&sredL[n0 + 1], l1);
            }
        }
    }
    __syncthreads();
    if (tid < CH) {
        atomicAdd(&g_sumf[chunk * CH + tid], sredF[tid]);
        atomicAdd(&g_suml[chunk * CH + tid], sredL[tid]);
    }
}

__global__ void __launch_bounds__(256) k_final(float* __restrict__ out) {
    __shared__ float sbuf[33];
    float acc = 0.f;
    for (int i = threadIdx.x; i < N_ROWS; i += 256) {
        float pf = g_posf[i], pl = g_posl[i];
        float lf = logf(__expf(LSCALE * pf) + g_sumf[i]) - LSCALE * pf;
        float ll = logf(__expf(LSCALE * pl) + g_suml[i]) - LSCALE * pl;
        acc += lf + AUXW * ll;
    }
    float tot = block_sum_bcast(acc, sbuf);
    if (threadIdx.x == 0) out[0] = tot * (1.0f / (float)N_ROWS);
}

// ---------------- launch --------------------------------------------------------
// Order puts k_scan at launch index 3 so the fixed ncu capture slot profiles it.
extern "C" void kernel_launch(void* const* d_in, const int* in_sizes, int n_in,
                              void* d_out, int out_size) {
    const float* h = (const float*)d_in[0];
    const float* w = (const float*)d_in[1];
    const int* tg = (const int*)d_in[2];
    float* out = (float*)d_out;
    (void)in_sizes; (void)n_in; (void)out_size;

    cudaFuncSetAttribute(k_main, cudaFuncAttributeMaxDynamicSharedMemorySize,
                         PIPE * STG_BYTES);

    k_zero<<<(NCHUNK * NBINS + 255) / 256, 256>>>();
    k_prep_w<<<VOCAB, 256>>>(w);
    k_prep_h<<<N_ROWS, 256>>>(h);
    k_scan<<<(VOCAB + 127) / 128, 256>>>();
    k_pos<<<N_ROWS, 256>>>(h, w, tg);
    k_thresh<<<NCHUNK, 256>>>();
    k_collect<<<dim3((VOCAB + 255) / 256, NCHUNK), 256>>>();
    k_main<<<dim3(NCAND / TM, NCHUNK), 256, PIPE * STG_BYTES>>>(tg);
    k_final<<<1, 256>>>(out);
}